// round 1
// baseline (speedup 1.0000x reference)
#include <cuda_runtime.h>
#include <math.h>

// Problem constants
#define B_   2
#define L_   2048
#define D_   2048
#define KD_  512
#define F_   5632
#define M_   (B_*L_)   // 4096 rows
#define H_   16
#define KVH_ 4
#define HD_  128

// ---------------- scratch (static device globals; no allocs allowed) -------
__device__ float g_h   [(size_t)M_ * D_];
__device__ float g_q   [(size_t)M_ * D_];
__device__ float g_k   [(size_t)M_ * KD_];
__device__ float g_v   [(size_t)M_ * KD_];
__device__ float g_att [(size_t)M_ * D_];
__device__ float g_x1  [(size_t)M_ * D_];
__device__ float g_h2  [(size_t)M_ * D_];
__device__ float g_gate[(size_t)M_ * F_];
__device__ float g_up  [(size_t)M_ * F_];

// ---------------- RMSNorm: one block per row (2048 cols) -------------------
__global__ __launch_bounds__(256) void rmsnorm_kernel(
    const float* __restrict__ x, const float* __restrict__ w,
    float* __restrict__ out)
{
    int row = blockIdx.x;
    const float4* xr = (const float4*)(x + (size_t)row * D_);
    const float4* wr = (const float4*)w;
    float4* orow = (float4*)(out + (size_t)row * D_);
    int t = threadIdx.x;

    float4 v0 = xr[t];
    float4 v1 = xr[t + 256];
    float ss = v0.x*v0.x + v0.y*v0.y + v0.z*v0.z + v0.w*v0.w
             + v1.x*v1.x + v1.y*v1.y + v1.z*v1.z + v1.w*v1.w;
    #pragma unroll
    for (int o = 16; o > 0; o >>= 1) ss += __shfl_xor_sync(0xffffffffu, ss, o);

    __shared__ float red[8];
    if ((t & 31) == 0) red[t >> 5] = ss;
    __syncthreads();
    float tot = red[0] + red[1] + red[2] + red[3] + red[4] + red[5] + red[6] + red[7];
    float norm = rsqrtf(tot * (1.0f / 2048.0f) + 1e-6f);

    float4 w0 = wr[t], w1 = wr[t + 256];
    float4 r0, r1;
    r0.x = v0.x*norm*w0.x; r0.y = v0.y*norm*w0.y; r0.z = v0.z*norm*w0.z; r0.w = v0.w*norm*w0.w;
    r1.x = v1.x*norm*w1.x; r1.y = v1.y*norm*w1.y; r1.z = v1.z*norm*w1.z; r1.w = v1.w*norm*w1.w;
    orow[t] = r0;
    orow[t + 256] = r1;
}

// ---------------- SGEMM: C[M,N] = A[M,K] @ B[N,K]^T (+bias) (+residual) ----
// 128x128 block tile, BK=8, 256 threads, 8x8 micro-tile per thread.
// All M,N,K here are multiples of 128/8 so no bounds checks.
template<bool HAS_BIAS, bool HAS_RES>
__global__ __launch_bounds__(256) void sgemm_kernel(
    const float* __restrict__ A, const float* __restrict__ Bm,
    const float* __restrict__ bias, const float* __restrict__ res,
    float* __restrict__ C, int M, int N, int K)
{
    __shared__ float As[8][128];
    __shared__ float Bs[8][128];

    const int tid = threadIdx.x;
    const int tx = tid & 15;
    const int ty = tid >> 4;
    const int lr = tid >> 1;          // loader row 0..127
    const int lc = (tid & 1) << 2;    // loader col 0 or 4

    const float* Ap = A  + (size_t)(blockIdx.y * 128 + lr) * K + lc;
    const float* Bp = Bm + (size_t)(blockIdx.x * 128 + lr) * K + lc;

    float acc[8][8];
    #pragma unroll
    for (int i = 0; i < 8; i++)
        #pragma unroll
        for (int j = 0; j < 8; j++) acc[i][j] = 0.0f;

    for (int k0 = 0; k0 < K; k0 += 8) {
        float4 a4 = *(const float4*)(Ap + k0);
        float4 b4 = *(const float4*)(Bp + k0);
        __syncthreads();
        As[lc+0][lr] = a4.x; As[lc+1][lr] = a4.y; As[lc+2][lr] = a4.z; As[lc+3][lr] = a4.w;
        Bs[lc+0][lr] = b4.x; Bs[lc+1][lr] = b4.y; Bs[lc+2][lr] = b4.z; Bs[lc+3][lr] = b4.w;
        __syncthreads();

        #pragma unroll
        for (int k = 0; k < 8; k++) {
            float ar[8], br[8];
            *(float4*)(ar)     = *(const float4*)(&As[k][ty * 8]);
            *(float4*)(ar + 4) = *(const float4*)(&As[k][ty * 8 + 4]);
            *(float4*)(br)     = *(const float4*)(&Bs[k][tx * 8]);
            *(float4*)(br + 4) = *(const float4*)(&Bs[k][tx * 8 + 4]);
            #pragma unroll
            for (int i = 0; i < 8; i++)
                #pragma unroll
                for (int j = 0; j < 8; j++)
                    acc[i][j] += ar[i] * br[j];
        }
    }

    #pragma unroll
    for (int i = 0; i < 8; i++) {
        int row = blockIdx.y * 128 + ty * 8 + i;
        int colbase = blockIdx.x * 128 + tx * 8;
        float* crow = C + (size_t)row * N + colbase;
        #pragma unroll
        for (int j = 0; j < 8; j += 4) {
            float4 v;
            v.x = acc[i][j]; v.y = acc[i][j+1]; v.z = acc[i][j+2]; v.w = acc[i][j+3];
            if (HAS_BIAS) {
                const float4 bb = *(const float4*)(bias + colbase + j);
                v.x += bb.x; v.y += bb.y; v.z += bb.z; v.w += bb.w;
            }
            if (HAS_RES) {
                const float4 rr = *(const float4*)(res + (size_t)row * N + colbase + j);
                v.x += rr.x; v.y += rr.y; v.z += rr.z; v.w += rr.w;
            }
            *(float4*)(crow + j) = v;
        }
    }
}

// ---------------- Flash attention (fp32, causal, GQA) ----------------------
// Q: [B,L,H*HD] row-major; K,V: [B,L,KVH*HD]; O: [B,L,H*HD]
// grid: (L/64, H, B). 256 threads (16x16). Tiles 64 (q) x 64 (k).
#define AT_BM 64
#define AT_BN 64
#define KS_STRIDE 129
#define ATT_SMEM ((64*128 + 64*KS_STRIDE + 64*128 + 64*64) * 4)
#define NEG_BIG (-1e30f)

__global__ __launch_bounds__(256) void attn_kernel(
    const float* __restrict__ Q, const float* __restrict__ K,
    const float* __restrict__ V, float* __restrict__ O)
{
    const int qi = blockIdx.x;
    const int h  = blockIdx.y;
    const int b  = blockIdx.z;
    const int kvh = h & (KVH_ - 1);

    extern __shared__ float sm[];
    float* Qs = sm;                      // [64][128]
    float* Ks = Qs + 64 * 128;           // [64][129]
    float* Vs = Ks + 64 * KS_STRIDE;     // [64][128]
    float* Ps = Vs + 64 * 128;           // [64][64]

    const int tid = threadIdx.x;
    const int tx = tid & 15;
    const int ty = tid >> 4;

    // Load Q tile (rows qi*64..+63, head slice)
    const float* qbase = Q + ((size_t)(b * L_ + qi * 64)) * D_ + h * HD_;
    for (int i = tid; i < 64 * 32; i += 256) {
        int r = i >> 5, c4 = i & 31;
        *(float4*)(Qs + r * 128 + c4 * 4) = *(const float4*)(qbase + (size_t)r * D_ + c4 * 4);
    }

    float acc[4][8];
    float m_i[4], l_i[4];
    #pragma unroll
    for (int i = 0; i < 4; i++) {
        m_i[i] = NEG_BIG; l_i[i] = 0.0f;
        #pragma unroll
        for (int d = 0; d < 8; d++) acc[i][d] = 0.0f;
    }
    const float scale = 0.08838834764831845f; // 1/sqrt(128)
    __syncthreads();

    for (int j = 0; j <= qi; j++) {
        __syncthreads();  // previous tile fully consumed
        const float* kbase = K + ((size_t)(b * L_ + j * 64)) * KD_ + kvh * HD_;
        const float* vbase = V + ((size_t)(b * L_ + j * 64)) * KD_ + kvh * HD_;
        for (int i = tid; i < 64 * 32; i += 256) {
            int r = i >> 5, c4 = i & 31;
            float4 kv = *(const float4*)(kbase + (size_t)r * KD_ + c4 * 4);
            Ks[r * KS_STRIDE + c4*4+0] = kv.x;
            Ks[r * KS_STRIDE + c4*4+1] = kv.y;
            Ks[r * KS_STRIDE + c4*4+2] = kv.z;
            Ks[r * KS_STRIDE + c4*4+3] = kv.w;
            *(float4*)(Vs + r * 128 + c4 * 4) = *(const float4*)(vbase + (size_t)r * KD_ + c4 * 4);
        }
        __syncthreads();

        // S = Q K^T  (each thread: rows ty*4..+3, cols tx*4..+3)
        float s[4][4];
        #pragma unroll
        for (int i = 0; i < 4; i++)
            #pragma unroll
            for (int jj = 0; jj < 4; jj++) s[i][jj] = 0.0f;

        const float* qrow = Qs + (ty * 4) * 128;
        const float* krow = Ks + (tx * 4) * KS_STRIDE;
        #pragma unroll 4
        for (int kk = 0; kk < 128; kk++) {
            float a0 = qrow[kk], a1 = qrow[128 + kk], a2 = qrow[256 + kk], a3 = qrow[384 + kk];
            float b0 = krow[kk], b1 = krow[KS_STRIDE + kk],
                  b2 = krow[2*KS_STRIDE + kk], b3 = krow[3*KS_STRIDE + kk];
            s[0][0] += a0*b0; s[0][1] += a0*b1; s[0][2] += a0*b2; s[0][3] += a0*b3;
            s[1][0] += a1*b0; s[1][1] += a1*b1; s[1][2] += a1*b2; s[1][3] += a1*b3;
            s[2][0] += a2*b0; s[2][1] += a2*b1; s[2][2] += a2*b2; s[2][3] += a2*b3;
            s[3][0] += a3*b0; s[3][1] += a3*b1; s[3][2] += a3*b2; s[3][3] += a3*b3;
        }

        const bool diag = (j == qi);
        #pragma unroll
        for (int i = 0; i < 4; i++) {
            int gq = qi * 64 + ty * 4 + i;
            float mloc = NEG_BIG;
            #pragma unroll
            for (int jj = 0; jj < 4; jj++) {
                float sv = s[i][jj] * scale;
                if (diag) {
                    int gk = j * 64 + tx * 4 + jj;
                    if (gk > gq) sv = NEG_BIG;
                }
                s[i][jj] = sv;
                mloc = fmaxf(mloc, sv);
            }
            #pragma unroll
            for (int o = 1; o < 16; o <<= 1)
                mloc = fmaxf(mloc, __shfl_xor_sync(0xffffffffu, mloc, o));
            float mnew = fmaxf(m_i[i], mloc);
            float lsum = 0.0f;
            float pv[4];
            #pragma unroll
            for (int jj = 0; jj < 4; jj++) {
                float p = __expf(s[i][jj] - mnew);
                pv[jj] = p; lsum += p;
            }
            #pragma unroll
            for (int o = 1; o < 16; o <<= 1)
                lsum += __shfl_xor_sync(0xffffffffu, lsum, o);
            float alpha = __expf(m_i[i] - mnew);
            m_i[i] = mnew;
            l_i[i] = l_i[i] * alpha + lsum;
            #pragma unroll
            for (int d = 0; d < 8; d++) acc[i][d] *= alpha;
            float* prow = Ps + (ty * 4 + i) * 64 + tx * 4;
            prow[0] = pv[0]; prow[1] = pv[1]; prow[2] = pv[2]; prow[3] = pv[3];
        }
        __syncthreads();

        // O += P V  (thread: rows ty*4..+3, dims tx*8..+7)
        #pragma unroll 2
        for (int c = 0; c < 64; c++) {
            float4 v0 = *(const float4*)(Vs + c * 128 + tx * 8);
            float4 v1 = *(const float4*)(Vs + c * 128 + tx * 8 + 4);
            #pragma unroll
            for (int i = 0; i < 4; i++) {
                float p = Ps[(ty * 4 + i) * 64 + c];
                acc[i][0] += p * v0.x; acc[i][1] += p * v0.y;
                acc[i][2] += p * v0.z; acc[i][3] += p * v0.w;
                acc[i][4] += p * v1.x; acc[i][5] += p * v1.y;
                acc[i][6] += p * v1.z; acc[i][7] += p * v1.w;
            }
        }
    }

    // Normalize + write
    float* obase = O + ((size_t)(b * L_ + qi * 64 + ty * 4)) * D_ + h * HD_ + tx * 8;
    #pragma unroll
    for (int i = 0; i < 4; i++) {
        float inv = 1.0f / l_i[i];
        float4 r0, r1;
        r0.x = acc[i][0]*inv; r0.y = acc[i][1]*inv; r0.z = acc[i][2]*inv; r0.w = acc[i][3]*inv;
        r1.x = acc[i][4]*inv; r1.y = acc[i][5]*inv; r1.z = acc[i][6]*inv; r1.w = acc[i][7]*inv;
        *(float4*)(obase + (size_t)i * D_)     = r0;
        *(float4*)(obase + (size_t)i * D_ + 4) = r1;
    }
}

// ---------------- SiLU(gate) * up  (in place into gate) --------------------
__global__ __launch_bounds__(256) void silu_mul_kernel(
    float* __restrict__ gate, const float* __restrict__ up, int n4)
{
    int i = blockIdx.x * blockDim.x + threadIdx.x;
    if (i >= n4) return;
    float4 g = ((float4*)gate)[i];
    float4 u = ((const float4*)up)[i];
    g.x = g.x * (1.0f / (1.0f + __expf(-g.x))) * u.x;
    g.y = g.y * (1.0f / (1.0f + __expf(-g.y))) * u.y;
    g.z = g.z * (1.0f / (1.0f + __expf(-g.z))) * u.z;
    g.w = g.w * (1.0f / (1.0f + __expf(-g.w))) * u.w;
    ((float4*)gate)[i] = g;
}

// ---------------- launch ---------------------------------------------------
extern "C" void kernel_launch(void* const* d_in, const int* in_sizes, int n_in,
                              void* d_out, int out_size)
{
    (void)in_sizes; (void)n_in; (void)out_size;
    const float* x      = (const float*)d_in[0];
    const float* ln1_w  = (const float*)d_in[1];
    const float* q_w    = (const float*)d_in[2];
    const float* q_b    = (const float*)d_in[3];
    const float* k_w    = (const float*)d_in[4];
    const float* k_b    = (const float*)d_in[5];
    const float* v_w    = (const float*)d_in[6];
    const float* v_b    = (const float*)d_in[7];
    const float* o_w    = (const float*)d_in[8];
    const float* ln2_w  = (const float*)d_in[9];
    const float* gate_w = (const float*)d_in[10];
    const float* up_w   = (const float*)d_in[11];
    const float* down_w = (const float*)d_in[12];
    float* out = (float*)d_out;

    float *h, *q, *k, *v, *att, *x1, *h2, *gate, *up;
    cudaGetSymbolAddress((void**)&h,    g_h);
    cudaGetSymbolAddress((void**)&q,    g_q);
    cudaGetSymbolAddress((void**)&k,    g_k);
    cudaGetSymbolAddress((void**)&v,    g_v);
    cudaGetSymbolAddress((void**)&att,  g_att);
    cudaGetSymbolAddress((void**)&x1,   g_x1);
    cudaGetSymbolAddress((void**)&h2,   g_h2);
    cudaGetSymbolAddress((void**)&gate, g_gate);
    cudaGetSymbolAddress((void**)&up,   g_up);

    cudaFuncSetAttribute(attn_kernel, cudaFuncAttributeMaxDynamicSharedMemorySize, ATT_SMEM);

    // 1. RMSNorm 1
    rmsnorm_kernel<<<M_, 256>>>(x, ln1_w, h);
    // 2-4. Q, K, V projections (with bias)
    sgemm_kernel<true , false><<<dim3(D_  / 128, M_ / 128), 256>>>(h, q_w, q_b, nullptr, q, M_, D_ , D_);
    sgemm_kernel<true , false><<<dim3(KD_ / 128, M_ / 128), 256>>>(h, k_w, k_b, nullptr, k, M_, KD_, D_);
    sgemm_kernel<true , false><<<dim3(KD_ / 128, M_ / 128), 256>>>(h, v_w, v_b, nullptr, v, M_, KD_, D_);
    // 5. causal GQA attention
    attn_kernel<<<dim3(L_ / 64, H_, B_), 256, ATT_SMEM>>>(q, k, v, att);
    // 6. O projection + residual (x)
    sgemm_kernel<false, true ><<<dim3(D_ / 128, M_ / 128), 256>>>(att, o_w, nullptr, x, x1, M_, D_, D_);
    // 7. RMSNorm 2
    rmsnorm_kernel<<<M_, 256>>>(x1, ln2_w, h2);
    // 8-9. gate / up projections
    sgemm_kernel<false, false><<<dim3(F_ / 128, M_ / 128), 256>>>(h2, gate_w, nullptr, nullptr, gate, M_, F_, D_);
    sgemm_kernel<false, false><<<dim3(F_ / 128, M_ / 128), 256>>>(h2, up_w  , nullptr, nullptr, up  , M_, F_, D_);
    // 10. silu(gate) * up
    {
        int n4 = (int)((size_t)M_ * F_ / 4);
        silu_mul_kernel<<<(n4 + 255) / 256, 256>>>(gate, up, n4);
    }
    // 11. down projection + residual (x1) -> output
    sgemm_kernel<false, true ><<<dim3(D_ / 128, M_ / 128), 256>>>(gate, down_w, nullptr, x1, out, M_, D_, F_);
}

// round 3
// speedup vs baseline: 1.5668x; 1.5668x over previous
#include <cuda_runtime.h>
#include <math.h>

// Problem constants
#define B_   2
#define L_   2048
#define D_   2048
#define KD_  512
#define F_   5632
#define M_   (B_*L_)   // 4096 rows
#define H_   16
#define KVH_ 4
#define HD_  128

// ---------------- scratch (static device globals; no allocs allowed) -------
__device__ float g_h   [(size_t)M_ * D_];
__device__ float g_q   [(size_t)M_ * D_];
__device__ float g_k   [(size_t)M_ * KD_];
__device__ float g_v   [(size_t)M_ * KD_];
__device__ float g_att [(size_t)M_ * D_];
__device__ float g_x1  [(size_t)M_ * D_];
__device__ float g_h2  [(size_t)M_ * D_];
__device__ float g_gate[(size_t)M_ * F_];
__device__ float g_up  [(size_t)M_ * F_];

// ---------------- RMSNorm: one block per row (2048 cols) -------------------
__global__ __launch_bounds__(256) void rmsnorm_kernel(
    const float* __restrict__ x, const float* __restrict__ w,
    float* __restrict__ out)
{
    int row = blockIdx.x;
    const float4* xr = (const float4*)(x + (size_t)row * D_);
    const float4* wr = (const float4*)w;
    float4* orow = (float4*)(out + (size_t)row * D_);
    int t = threadIdx.x;

    float4 v0 = xr[t];
    float4 v1 = xr[t + 256];
    float ss = v0.x*v0.x + v0.y*v0.y + v0.z*v0.z + v0.w*v0.w
             + v1.x*v1.x + v1.y*v1.y + v1.z*v1.z + v1.w*v1.w;
    #pragma unroll
    for (int o = 16; o > 0; o >>= 1) ss += __shfl_xor_sync(0xffffffffu, ss, o);

    __shared__ float red[8];
    if ((t & 31) == 0) red[t >> 5] = ss;
    __syncthreads();
    float tot = red[0] + red[1] + red[2] + red[3] + red[4] + red[5] + red[6] + red[7];
    float norm = rsqrtf(tot * (1.0f / 2048.0f) + 1e-6f);

    float4 w0 = wr[t], w1 = wr[t + 256];
    float4 r0, r1;
    r0.x = v0.x*norm*w0.x; r0.y = v0.y*norm*w0.y; r0.z = v0.z*norm*w0.z; r0.w = v0.w*norm*w0.w;
    r1.x = v1.x*norm*w1.x; r1.y = v1.y*norm*w1.y; r1.z = v1.z*norm*w1.z; r1.w = v1.w*norm*w1.w;
    orow[t] = r0;
    orow[t + 256] = r1;
}

// ================= 3xTF32 tensor-core GEMM =================================
// C[M,N] = A[M,K] @ W[N,K]^T  (+bias) (+residual)
// Block tile 128x256, BK=32, 256 threads (8 warps, each 64x64).
// Each operand split a = hi + lo (hi = mantissa-truncated); 3 MMAs per pair:
//   acc += a_hi*b_lo + a_lo*b_hi + a_hi*b_hi   (fp32-accurate, ~1e-7 rel)
#define BM 128
#define BN 256
#define BK 32
#define ASTRIDE 36
#define SA_ELEMS (BM*ASTRIDE)
#define SB_ELEMS (BN*ASTRIDE)
#define GEMM_SMEM ((SA_ELEMS + SB_ELEMS) * 2 * 4)

__device__ __forceinline__ unsigned smem_u32(const void* p) {
    return (unsigned)__cvta_generic_to_shared(p);
}

__device__ __forceinline__ void split32(float a, unsigned& hi, unsigned& lo) {
    unsigned h = __float_as_uint(a) & 0xffffe000u;  // truncate low 13 mantissa bits
    hi = h;
    lo = __float_as_uint(a - __uint_as_float(h));   // exact remainder
}

#define MMA_TF32(d, a0, a1, a2, a3, b0, b1)                                   \
    asm volatile(                                                             \
        "mma.sync.aligned.m16n8k8.row.col.f32.tf32.tf32.f32 "                 \
        "{%0,%1,%2,%3}, {%4,%5,%6,%7}, {%8,%9}, {%0,%1,%2,%3};\n"             \
        : "+f"(d[0]), "+f"(d[1]), "+f"(d[2]), "+f"(d[3])                      \
        : "r"(a0), "r"(a1), "r"(a2), "r"(a3), "r"(b0), "r"(b1))

template<bool HAS_BIAS, bool HAS_RES>
__global__ __launch_bounds__(256, 1) void tgemm_kernel(
    const float* __restrict__ A, const float* __restrict__ W,
    const float* __restrict__ bias, const float* __restrict__ res,
    float* __restrict__ C, int M, int N, int K)
{
    extern __shared__ float sm[];
    float* As = sm;                    // [2][BM][ASTRIDE]
    float* Bs = sm + 2 * SA_ELEMS;     // [2][BN][ASTRIDE]

    const int tid  = threadIdx.x;
    const int lane = tid & 31;
    const int wid  = tid >> 5;
    const int wm   = wid & 1;          // warp row (0..1) -> 64 rows each
    const int wn   = wid >> 1;         // warp col (0..3) -> 64 cols each
    const int gid  = lane >> 2;        // 0..7
    const int tig  = lane & 3;         // 0..3

    const int bm = blockIdx.y * BM;
    const int bn = blockIdx.x * BN;

    const int lr = tid >> 3;           // loader row 0..31
    const int lc = (tid & 7) * 4;      // loader float col 0,4,..,28

    const float* Ag = A + (size_t)(bm + lr) * K + lc;
    const float* Bg = W + (size_t)(bn + lr) * K + lc;

    float acc[4][8][4];
    #pragma unroll
    for (int i = 0; i < 4; i++)
        #pragma unroll
        for (int j = 0; j < 8; j++)
            #pragma unroll
            for (int c = 0; c < 4; c++) acc[i][j][c] = 0.0f;

    const int T = K / BK;

    // ---- prefetch tile 0 ----
    {
        float* as = As;
        float* bs = Bs;
        #pragma unroll
        for (int r = 0; r < BM; r += 32) {
            unsigned dst = smem_u32(as + (size_t)(lr + r) * ASTRIDE + lc);
            asm volatile("cp.async.cg.shared.global [%0], [%1], 16;\n"
                         :: "r"(dst), "l"(Ag + (size_t)r * K));
        }
        #pragma unroll
        for (int r = 0; r < BN; r += 32) {
            unsigned dst = smem_u32(bs + (size_t)(lr + r) * ASTRIDE + lc);
            asm volatile("cp.async.cg.shared.global [%0], [%1], 16;\n"
                         :: "r"(dst), "l"(Bg + (size_t)r * K));
        }
        asm volatile("cp.async.commit_group;\n");
    }

    for (int t = 0; t < T; t++) {
        asm volatile("cp.async.wait_group 0;\n");
        __syncthreads();

        if (t + 1 < T) {
            int buf = (t + 1) & 1;
            float* as = As + buf * SA_ELEMS;
            float* bs = Bs + buf * SB_ELEMS;
            const float* ag = Ag + (size_t)(t + 1) * BK;
            const float* bg = Bg + (size_t)(t + 1) * BK;
            #pragma unroll
            for (int r = 0; r < BM; r += 32) {
                unsigned dst = smem_u32(as + (size_t)(lr + r) * ASTRIDE + lc);
                asm volatile("cp.async.cg.shared.global [%0], [%1], 16;\n"
                             :: "r"(dst), "l"(ag + (size_t)r * K));
            }
            #pragma unroll
            for (int r = 0; r < BN; r += 32) {
                unsigned dst = smem_u32(bs + (size_t)(lr + r) * ASTRIDE + lc);
                asm volatile("cp.async.cg.shared.global [%0], [%1], 16;\n"
                             :: "r"(dst), "l"(bg + (size_t)r * K));
            }
            asm volatile("cp.async.commit_group;\n");
        }

        const float* as = As + (t & 1) * SA_ELEMS;
        const float* bs = Bs + (t & 1) * SB_ELEMS;

        #pragma unroll
        for (int ks = 0; ks < 4; ks++) {
            const int k = ks * 8;
            unsigned afh[4][4], afl[4][4], bfh[8][2], bfl[8][2];
            #pragma unroll
            for (int i = 0; i < 4; i++) {
                const float* p = as + (size_t)(wm * 64 + i * 16 + gid) * ASTRIDE + k + tig;
                split32(p[0],               afh[i][0], afl[i][0]);
                split32(p[8 * ASTRIDE],     afh[i][1], afl[i][1]);
                split32(p[4],               afh[i][2], afl[i][2]);
                split32(p[8 * ASTRIDE + 4], afh[i][3], afl[i][3]);
            }
            #pragma unroll
            for (int j = 0; j < 8; j++) {
                const float* p = bs + (size_t)(wn * 64 + j * 8 + gid) * ASTRIDE + k + tig;
                split32(p[0], bfh[j][0], bfl[j][0]);
                split32(p[4], bfh[j][1], bfl[j][1]);
            }
            #pragma unroll
            for (int i = 0; i < 4; i++)
                #pragma unroll
                for (int j = 0; j < 8; j++) {
                    MMA_TF32(acc[i][j], afh[i][0], afh[i][1], afh[i][2], afh[i][3],
                             bfl[j][0], bfl[j][1]);
                    MMA_TF32(acc[i][j], afl[i][0], afl[i][1], afl[i][2], afl[i][3],
                             bfh[j][0], bfh[j][1]);
                    MMA_TF32(acc[i][j], afh[i][0], afh[i][1], afh[i][2], afh[i][3],
                             bfh[j][0], bfh[j][1]);
                }
        }
        __syncthreads();
    }

    // ---- epilogue ----
    #pragma unroll
    for (int i = 0; i < 4; i++) {
        const int r0 = bm + wm * 64 + i * 16 + gid;
        #pragma unroll
        for (int j = 0; j < 8; j++) {
            const int col = bn + wn * 64 + j * 8 + tig * 2;
            float2 v0 = make_float2(acc[i][j][0], acc[i][j][1]);
            float2 v1 = make_float2(acc[i][j][2], acc[i][j][3]);
            if (HAS_BIAS) {
                float2 bb = *(const float2*)(bias + col);
                v0.x += bb.x; v0.y += bb.y; v1.x += bb.x; v1.y += bb.y;
            }
            if (HAS_RES) {
                float2 q0 = *(const float2*)(res + (size_t)r0 * N + col);
                float2 q1 = *(const float2*)(res + (size_t)(r0 + 8) * N + col);
                v0.x += q0.x; v0.y += q0.y; v1.x += q1.x; v1.y += q1.y;
            }
            *(float2*)(C + (size_t)r0 * N + col) = v0;
            *(float2*)(C + (size_t)(r0 + 8) * N + col) = v1;
        }
    }
}

// ---------------- Flash attention (fp32, causal, GQA) ----------------------
#define KS_STRIDE 129
#define ATT_SMEM ((64*128 + 64*KS_STRIDE + 64*128 + 64*64) * 4)
#define NEG_BIG (-1e30f)

__global__ __launch_bounds__(256) void attn_kernel(
    const float* __restrict__ Q, const float* __restrict__ K,
    const float* __restrict__ V, float* __restrict__ O)
{
    const int qi = blockIdx.x;
    const int h  = blockIdx.y;
    const int b  = blockIdx.z;
    const int kvh = h & (KVH_ - 1);

    extern __shared__ float sm[];
    float* Qs = sm;                      // [64][128]
    float* Ks = Qs + 64 * 128;           // [64][129]
    float* Vs = Ks + 64 * KS_STRIDE;     // [64][128]
    float* Ps = Vs + 64 * 128;           // [64][64]

    const int tid = threadIdx.x;
    const int tx = tid & 15;
    const int ty = tid >> 4;

    const float* qbase = Q + ((size_t)(b * L_ + qi * 64)) * D_ + h * HD_;
    for (int i = tid; i < 64 * 32; i += 256) {
        int r = i >> 5, c4 = i & 31;
        *(float4*)(Qs + r * 128 + c4 * 4) = *(const float4*)(qbase + (size_t)r * D_ + c4 * 4);
    }

    float acc[4][8];
    float m_i[4], l_i[4];
    #pragma unroll
    for (int i = 0; i < 4; i++) {
        m_i[i] = NEG_BIG; l_i[i] = 0.0f;
        #pragma unroll
        for (int d = 0; d < 8; d++) acc[i][d] = 0.0f;
    }
    const float scale = 0.08838834764831845f;
    __syncthreads();

    for (int j = 0; j <= qi; j++) {
        __syncthreads();
        const float* kbase = K + ((size_t)(b * L_ + j * 64)) * KD_ + kvh * HD_;
        const float* vbase = V + ((size_t)(b * L_ + j * 64)) * KD_ + kvh * HD_;
        for (int i = tid; i < 64 * 32; i += 256) {
            int r = i >> 5, c4 = i & 31;
            float4 kv = *(const float4*)(kbase + (size_t)r * KD_ + c4 * 4);
            Ks[r * KS_STRIDE + c4*4+0] = kv.x;
            Ks[r * KS_STRIDE + c4*4+1] = kv.y;
            Ks[r * KS_STRIDE + c4*4+2] = kv.z;
            Ks[r * KS_STRIDE + c4*4+3] = kv.w;
            *(float4*)(Vs + r * 128 + c4 * 4) = *(const float4*)(vbase + (size_t)r * KD_ + c4 * 4);
        }
        __syncthreads();

        float s[4][4];
        #pragma unroll
        for (int i = 0; i < 4; i++)
            #pragma unroll
            for (int jj = 0; jj < 4; jj++) s[i][jj] = 0.0f;

        const float* qrow = Qs + (ty * 4) * 128;
        const float* krow = Ks + (tx * 4) * KS_STRIDE;
        #pragma unroll 4
        for (int kk = 0; kk < 128; kk++) {
            float a0 = qrow[kk], a1 = qrow[128 + kk], a2 = qrow[256 + kk], a3 = qrow[384 + kk];
            float b0 = krow[kk], b1 = krow[KS_STRIDE + kk],
                  b2 = krow[2*KS_STRIDE + kk], b3 = krow[3*KS_STRIDE + kk];
            s[0][0] += a0*b0; s[0][1] += a0*b1; s[0][2] += a0*b2; s[0][3] += a0*b3;
            s[1][0] += a1*b0; s[1][1] += a1*b1; s[1][2] += a1*b2; s[1][3] += a1*b3;
            s[2][0] += a2*b0; s[2][1] += a2*b1; s[2][2] += a2*b2; s[2][3] += a2*b3;
            s[3][0] += a3*b0; s[3][1] += a3*b1; s[3][2] += a3*b2; s[3][3] += a3*b3;
        }

        const bool diag = (j == qi);
        #pragma unroll
        for (int i = 0; i < 4; i++) {
            int gq = qi * 64 + ty * 4 + i;
            float mloc = NEG_BIG;
            #pragma unroll
            for (int jj = 0; jj < 4; jj++) {
                float sv = s[i][jj] * scale;
                if (diag) {
                    int gk = j * 64 + tx * 4 + jj;
                    if (gk > gq) sv = NEG_BIG;
                }
                s[i][jj] = sv;
                mloc = fmaxf(mloc, sv);
            }
            #pragma unroll
            for (int o = 1; o < 16; o <<= 1)
                mloc = fmaxf(mloc, __shfl_xor_sync(0xffffffffu, mloc, o));
            float mnew = fmaxf(m_i[i], mloc);
            float lsum = 0.0f;
            float pv[4];
            #pragma unroll
            for (int jj = 0; jj < 4; jj++) {
                float p = __expf(s[i][jj] - mnew);
                pv[jj] = p; lsum += p;
            }
            #pragma unroll
            for (int o = 1; o < 16; o <<= 1)
                lsum += __shfl_xor_sync(0xffffffffu, lsum, o);
            float alpha = __expf(m_i[i] - mnew);
            m_i[i] = mnew;
            l_i[i] = l_i[i] * alpha + lsum;
            #pragma unroll
            for (int d = 0; d < 8; d++) acc[i][d] *= alpha;
            float* prow = Ps + (ty * 4 + i) * 64 + tx * 4;
            prow[0] = pv[0]; prow[1] = pv[1]; prow[2] = pv[2]; prow[3] = pv[3];
        }
        __syncthreads();

        #pragma unroll 2
        for (int c = 0; c < 64; c++) {
            float4 v0 = *(const float4*)(Vs + c * 128 + tx * 8);
            float4 v1 = *(const float4*)(Vs + c * 128 + tx * 8 + 4);
            #pragma unroll
            for (int i = 0; i < 4; i++) {
                float p = Ps[(ty * 4 + i) * 64 + c];
                acc[i][0] += p * v0.x; acc[i][1] += p * v0.y;
                acc[i][2] += p * v0.z; acc[i][3] += p * v0.w;
                acc[i][4] += p * v1.x; acc[i][5] += p * v1.y;
                acc[i][6] += p * v1.z; acc[i][7] += p * v1.w;
            }
        }
    }

    float* obase = O + ((size_t)(b * L_ + qi * 64 + ty * 4)) * D_ + h * HD_ + tx * 8;
    #pragma unroll
    for (int i = 0; i < 4; i++) {
        float inv = 1.0f / l_i[i];
        float4 r0, r1;
        r0.x = acc[i][0]*inv; r0.y = acc[i][1]*inv; r0.z = acc[i][2]*inv; r0.w = acc[i][3]*inv;
        r1.x = acc[i][4]*inv; r1.y = acc[i][5]*inv; r1.z = acc[i][6]*inv; r1.w = acc[i][7]*inv;
        *(float4*)(obase + (size_t)i * D_)     = r0;
        *(float4*)(obase + (size_t)i * D_ + 4) = r1;
    }
}

// ---------------- SiLU(gate) * up  (in place into gate) --------------------
__global__ __launch_bounds__(256) void silu_mul_kernel(
    float* __restrict__ gate, const float* __restrict__ up, int n4)
{
    int i = blockIdx.x * blockDim.x + threadIdx.x;
    if (i >= n4) return;
    float4 g = ((float4*)gate)[i];
    float4 u = ((const float4*)up)[i];
    g.x = g.x * (1.0f / (1.0f + __expf(-g.x))) * u.x;
    g.y = g.y * (1.0f / (1.0f + __expf(-g.y))) * u.y;
    g.z = g.z * (1.0f / (1.0f + __expf(-g.z))) * u.z;
    g.w = g.w * (1.0f / (1.0f + __expf(-g.w))) * u.w;
    ((float4*)gate)[i] = g;
}

// ---------------- launch ---------------------------------------------------
extern "C" void kernel_launch(void* const* d_in, const int* in_sizes, int n_in,
                              void* d_out, int out_size)
{
    (void)in_sizes; (void)n_in; (void)out_size;
    const float* x      = (const float*)d_in[0];
    const float* ln1_w  = (const float*)d_in[1];
    const float* q_w    = (const float*)d_in[2];
    const float* q_b    = (const float*)d_in[3];
    const float* k_w    = (const float*)d_in[4];
    const float* k_b    = (const float*)d_in[5];
    const float* v_w    = (const float*)d_in[6];
    const float* v_b    = (const float*)d_in[7];
    const float* o_w    = (const float*)d_in[8];
    const float* ln2_w  = (const float*)d_in[9];
    const float* gate_w = (const float*)d_in[10];
    const float* up_w   = (const float*)d_in[11];
    const float* down_w = (const float*)d_in[12];
    float* out = (float*)d_out;

    float *h, *q, *k, *v, *att, *x1, *h2, *gate, *up;
    cudaGetSymbolAddress((void**)&h,    g_h);
    cudaGetSymbolAddress((void**)&q,    g_q);
    cudaGetSymbolAddress((void**)&k,    g_k);
    cudaGetSymbolAddress((void**)&v,    g_v);
    cudaGetSymbolAddress((void**)&att,  g_att);
    cudaGetSymbolAddress((void**)&x1,   g_x1);
    cudaGetSymbolAddress((void**)&h2,   g_h2);
    cudaGetSymbolAddress((void**)&gate, g_gate);
    cudaGetSymbolAddress((void**)&up,   g_up);

    cudaFuncSetAttribute(attn_kernel, cudaFuncAttributeMaxDynamicSharedMemorySize, ATT_SMEM);
    cudaFuncSetAttribute(tgemm_kernel<true , false>, cudaFuncAttributeMaxDynamicSharedMemorySize, GEMM_SMEM);
    cudaFuncSetAttribute(tgemm_kernel<false, true >, cudaFuncAttributeMaxDynamicSharedMemorySize, GEMM_SMEM);
    cudaFuncSetAttribute(tgemm_kernel<false, false>, cudaFuncAttributeMaxDynamicSharedMemorySize, GEMM_SMEM);

    // 1. RMSNorm 1
    rmsnorm_kernel<<<M_, 256>>>(x, ln1_w, h);
    // 2-4. Q, K, V projections (with bias) -- 3xTF32 tensor cores
    tgemm_kernel<true , false><<<dim3(D_  / BN, M_ / BM), 256, GEMM_SMEM>>>(h, q_w, q_b, nullptr, q, M_, D_ , D_);
    tgemm_kernel<true , false><<<dim3(KD_ / BN, M_ / BM), 256, GEMM_SMEM>>>(h, k_w, k_b, nullptr, k, M_, KD_, D_);
    tgemm_kernel<true , false><<<dim3(KD_ / BN, M_ / BM), 256, GEMM_SMEM>>>(h, v_w, v_b, nullptr, v, M_, KD_, D_);
    // 5. causal GQA attention
    attn_kernel<<<dim3(L_ / 64, H_, B_), 256, ATT_SMEM>>>(q, k, v, att);
    // 6. O projection + residual (x)
    tgemm_kernel<false, true ><<<dim3(D_ / BN, M_ / BM), 256, GEMM_SMEM>>>(att, o_w, nullptr, x, x1, M_, D_, D_);
    // 7. RMSNorm 2
    rmsnorm_kernel<<<M_, 256>>>(x1, ln2_w, h2);
    // 8-9. gate / up projections
    tgemm_kernel<false, false><<<dim3(F_ / BN, M_ / BM), 256, GEMM_SMEM>>>(h2, gate_w, nullptr, nullptr, gate, M_, F_, D_);
    tgemm_kernel<false, false><<<dim3(F_ / BN, M_ / BM), 256, GEMM_SMEM>>>(h2, up_w  , nullptr, nullptr, up  , M_, F_, D_);
    // 10. silu(gate) * up
    {
        int n4 = (int)((size_t)M_ * F_ / 4);
        silu_mul_kernel<<<(n4 + 255) / 256, 256>>>(gate, up, n4);
    }
    // 11. down projection + residual (x1) -> output
    tgemm_kernel<false, true ><<<dim3(D_ / BN, M_ / BM), 256, GEMM_SMEM>>>(gate, down_w, nullptr, x1, out, M_, D_, F_);
}

// round 7
// speedup vs baseline: 1.7730x; 1.1316x over previous
#include <cuda_runtime.h>
#include <math.h>

// Problem constants
#define B_   2
#define L_   2048
#define D_   2048
#define KD_  512
#define F_   5632
#define M_   (B_*L_)   // 4096 rows
#define H_   16
#define KVH_ 4
#define HD_  128

// ---------------- scratch (static device globals; no allocs allowed) -------
__device__ float g_h   [(size_t)M_ * D_];
__device__ float g_q   [(size_t)M_ * D_];
__device__ float g_k   [(size_t)M_ * KD_];
__device__ float g_v   [(size_t)M_ * KD_];
__device__ float g_att [(size_t)M_ * D_];
__device__ float g_x1  [(size_t)M_ * D_];
__device__ float g_h2  [(size_t)M_ * D_];
__device__ float g_gate[(size_t)M_ * F_];
__device__ float g_up  [(size_t)M_ * F_];

__device__ __forceinline__ unsigned smem_u32(const void* p) {
    return (unsigned)__cvta_generic_to_shared(p);
}

__device__ __forceinline__ void split32(float a, unsigned& hi, unsigned& lo) {
    unsigned h = __float_as_uint(a) & 0xffffe000u;  // truncate low 13 mantissa bits
    hi = h;
    lo = __float_as_uint(a - __uint_as_float(h));   // exact remainder
}

#define MMA_TF32(d, a0, a1, a2, a3, b0, b1)                                   \
    asm volatile(                                                             \
        "mma.sync.aligned.m16n8k8.row.col.f32.tf32.tf32.f32 "                 \
        "{%0,%1,%2,%3}, {%4,%5,%6,%7}, {%8,%9}, {%0,%1,%2,%3};\n"             \
        : "+f"(d[0]), "+f"(d[1]), "+f"(d[2]), "+f"(d[3])                      \
        : "r"(a0), "r"(a1), "r"(a2), "r"(a3), "r"(b0), "r"(b1))

// ---------------- RMSNorm: one block per row (2048 cols) -------------------
__global__ __launch_bounds__(256) void rmsnorm_kernel(
    const float* __restrict__ x, const float* __restrict__ w,
    float* __restrict__ out)
{
    int row = blockIdx.x;
    const float4* xr = (const float4*)(x + (size_t)row * D_);
    const float4* wr = (const float4*)w;
    float4* orow = (float4*)(out + (size_t)row * D_);
    int t = threadIdx.x;

    float4 v0 = xr[t];
    float4 v1 = xr[t + 256];
    float ss = v0.x*v0.x + v0.y*v0.y + v0.z*v0.z + v0.w*v0.w
             + v1.x*v1.x + v1.y*v1.y + v1.z*v1.z + v1.w*v1.w;
    #pragma unroll
    for (int o = 16; o > 0; o >>= 1) ss += __shfl_xor_sync(0xffffffffu, ss, o);

    __shared__ float red[8];
    if ((t & 31) == 0) red[t >> 5] = ss;
    __syncthreads();
    float tot = red[0] + red[1] + red[2] + red[3] + red[4] + red[5] + red[6] + red[7];
    float norm = rsqrtf(tot * (1.0f / 2048.0f) + 1e-6f);

    float4 w0 = wr[t], w1 = wr[t + 256];
    float4 r0, r1;
    r0.x = v0.x*norm*w0.x; r0.y = v0.y*norm*w0.y; r0.z = v0.z*norm*w0.z; r0.w = v0.w*norm*w0.w;
    r1.x = v1.x*norm*w1.x; r1.y = v1.y*norm*w1.y; r1.z = v1.z*norm*w1.z; r1.w = v1.w*norm*w1.w;
    orow[t] = r0;
    orow[t + 256] = r1;
}

// ================= 3xTF32 tensor-core GEMM =================================
#define BM 128
#define BN 256
#define BK 32
#define ASTRIDE 36
#define SA_ELEMS (BM*ASTRIDE)
#define SB_ELEMS (BN*ASTRIDE)
#define GEMM_SMEM ((SA_ELEMS + SB_ELEMS) * 2 * 4)

template<bool HAS_BIAS, bool HAS_RES>
__global__ __launch_bounds__(256, 1) void tgemm_kernel(
    const float* __restrict__ A, const float* __restrict__ W,
    const float* __restrict__ bias, const float* __restrict__ res,
    float* __restrict__ C, int M, int N, int K)
{
    extern __shared__ float sm[];
    float* As = sm;                    // [2][BM][ASTRIDE]
    float* Bs = sm + 2 * SA_ELEMS;     // [2][BN][ASTRIDE]

    const int tid  = threadIdx.x;
    const int lane = tid & 31;
    const int wid  = tid >> 5;
    const int wm   = wid & 1;
    const int wn   = wid >> 1;
    const int gid  = lane >> 2;
    const int tig  = lane & 3;

    const int bm = blockIdx.y * BM;
    const int bn = blockIdx.x * BN;

    const int lr = tid >> 3;
    const int lc = (tid & 7) * 4;

    const float* Ag = A + (size_t)(bm + lr) * K + lc;
    const float* Bg = W + (size_t)(bn + lr) * K + lc;

    float acc[4][8][4];
    #pragma unroll
    for (int i = 0; i < 4; i++)
        #pragma unroll
        for (int j = 0; j < 8; j++)
            #pragma unroll
            for (int c = 0; c < 4; c++) acc[i][j][c] = 0.0f;

    const int T = K / BK;

    {
        float* as = As;
        float* bs = Bs;
        #pragma unroll
        for (int r = 0; r < BM; r += 32) {
            unsigned dst = smem_u32(as + (size_t)(lr + r) * ASTRIDE + lc);
            asm volatile("cp.async.cg.shared.global [%0], [%1], 16;\n"
                         :: "r"(dst), "l"(Ag + (size_t)r * K));
        }
        #pragma unroll
        for (int r = 0; r < BN; r += 32) {
            unsigned dst = smem_u32(bs + (size_t)(lr + r) * ASTRIDE + lc);
            asm volatile("cp.async.cg.shared.global [%0], [%1], 16;\n"
                         :: "r"(dst), "l"(Bg + (size_t)r * K));
        }
        asm volatile("cp.async.commit_group;\n");
    }

    for (int t = 0; t < T; t++) {
        asm volatile("cp.async.wait_group 0;\n");
        __syncthreads();

        if (t + 1 < T) {
            int buf = (t + 1) & 1;
            float* as = As + buf * SA_ELEMS;
            float* bs = Bs + buf * SB_ELEMS;
            const float* ag = Ag + (size_t)(t + 1) * BK;
            const float* bg = Bg + (size_t)(t + 1) * BK;
            #pragma unroll
            for (int r = 0; r < BM; r += 32) {
                unsigned dst = smem_u32(as + (size_t)(lr + r) * ASTRIDE + lc);
                asm volatile("cp.async.cg.shared.global [%0], [%1], 16;\n"
                             :: "r"(dst), "l"(ag + (size_t)r * K));
            }
            #pragma unroll
            for (int r = 0; r < BN; r += 32) {
                unsigned dst = smem_u32(bs + (size_t)(lr + r) * ASTRIDE + lc);
                asm volatile("cp.async.cg.shared.global [%0], [%1], 16;\n"
                             :: "r"(dst), "l"(bg + (size_t)r * K));
            }
            asm volatile("cp.async.commit_group;\n");
        }

        const float* as = As + (t & 1) * SA_ELEMS;
        const float* bs = Bs + (t & 1) * SB_ELEMS;

        #pragma unroll
        for (int ks = 0; ks < 4; ks++) {
            const int k = ks * 8;
            unsigned afh[4][4], afl[4][4], bfh[8][2], bfl[8][2];
            #pragma unroll
            for (int i = 0; i < 4; i++) {
                const float* p = as + (size_t)(wm * 64 + i * 16 + gid) * ASTRIDE + k + tig;
                split32(p[0],               afh[i][0], afl[i][0]);
                split32(p[8 * ASTRIDE],     afh[i][1], afl[i][1]);
                split32(p[4],               afh[i][2], afl[i][2]);
                split32(p[8 * ASTRIDE + 4], afh[i][3], afl[i][3]);
            }
            #pragma unroll
            for (int j = 0; j < 8; j++) {
                const float* p = bs + (size_t)(wn * 64 + j * 8 + gid) * ASTRIDE + k + tig;
                split32(p[0], bfh[j][0], bfl[j][0]);
                split32(p[4], bfh[j][1], bfl[j][1]);
            }
            #pragma unroll
            for (int i = 0; i < 4; i++)
                #pragma unroll
                for (int j = 0; j < 8; j++) {
                    MMA_TF32(acc[i][j], afh[i][0], afh[i][1], afh[i][2], afh[i][3],
                             bfl[j][0], bfl[j][1]);
                    MMA_TF32(acc[i][j], afl[i][0], afl[i][1], afl[i][2], afl[i][3],
                             bfh[j][0], bfh[j][1]);
                    MMA_TF32(acc[i][j], afh[i][0], afh[i][1], afh[i][2], afh[i][3],
                             bfh[j][0], bfh[j][1]);
                }
        }
        __syncthreads();
    }

    #pragma unroll
    for (int i = 0; i < 4; i++) {
        const int r0 = bm + wm * 64 + i * 16 + gid;
        #pragma unroll
        for (int j = 0; j < 8; j++) {
            const int col = bn + wn * 64 + j * 8 + tig * 2;
            float2 v0 = make_float2(acc[i][j][0], acc[i][j][1]);
            float2 v1 = make_float2(acc[i][j][2], acc[i][j][3]);
            if (HAS_BIAS) {
                float2 bb = *(const float2*)(bias + col);
                v0.x += bb.x; v0.y += bb.y; v1.x += bb.x; v1.y += bb.y;
            }
            if (HAS_RES) {
                float2 q0 = *(const float2*)(res + (size_t)r0 * N + col);
                float2 q1 = *(const float2*)(res + (size_t)(r0 + 8) * N + col);
                v0.x += q0.x; v0.y += q0.y; v1.x += q1.x; v1.y += q1.y;
            }
            *(float2*)(C + (size_t)r0 * N + col) = v0;
            *(float2*)(C + (size_t)(r0 + 8) * N + col) = v1;
        }
    }
}

// ================= 3xTF32 tensor-core flash attention ======================
// Per CTA: 128 q rows, one (b, h). KV tiles of 64, double-buffered cp.async.
// 8 warps: wm=wid&3 (32 q-rows each), wn=wid>>2 (S: 32 kv cols; PV: 64 hd).
// smem floats: Qs[128][128] swz, Ks 2x[64][128] swz, Vs 2x[64][128] swzV,
//              Ps[128][64] swz, Al[128]
#define ATT2_SMEM (57472 * 4)

__device__ __forceinline__ void attn_load_kv(
    const float* kg, const float* vg, float* Ksb, float* Vsb, int tid)
{
    #pragma unroll
    for (int it = 0; it < 8; it++) {
        int idx = tid + it * 256;
        int r = idx >> 5, c4 = (idx & 31) * 4;
        unsigned kd = smem_u32(Ksb + (size_t)r * 128 + (c4 ^ ((r & 7) << 2)));
        asm volatile("cp.async.cg.shared.global [%0], [%1], 16;\n"
                     :: "r"(kd), "l"(kg + (size_t)r * KD_ + c4));
        unsigned vd = smem_u32(Vsb + (size_t)r * 128 + (c4 ^ ((r & 3) << 3)));
        asm volatile("cp.async.cg.shared.global [%0], [%1], 16;\n"
                     :: "r"(vd), "l"(vg + (size_t)r * KD_ + c4));
    }
}

__global__ __launch_bounds__(256, 1) void fattn_kernel(
    const float* __restrict__ Q, const float* __restrict__ K,
    const float* __restrict__ V, float* __restrict__ O)
{
    const int qi = (int)(gridDim.x - 1 - blockIdx.x);   // heavy diagonals first
    const int h  = blockIdx.y;
    const int b  = blockIdx.z;
    const int kvh = h & (KVH_ - 1);

    extern __shared__ float sm[];
    float* Qs = sm;              // [128][128] swizzled (col ^ (row&7)<<2)
    float* Ks = sm + 16384;      // 2 x [64][128] swizzled same
    float* Vs = sm + 32768;      // 2 x [64][128] swizzled (col ^ (row&3)<<3)
    float* Ps = sm + 49152;      // [128][64] swizzled (col ^ (row&7)<<2)
    float* Al = sm + 57344;      // [128]

    const int tid  = threadIdx.x;
    const int lane = tid & 31;
    const int wid  = tid >> 5;
    const int wm   = wid & 3;
    const int wn   = wid >> 2;
    const int gid  = lane >> 2;
    const int tig  = lane & 3;
    const int swa  = gid << 2;   // A/B fragment row swizzle (row&7 == gid)
    const int swv  = tig << 3;   // V fragment row swizzle (row&3 == tig)

    // ---- Q tile load (once) ----
    const float* qg = Q + ((size_t)(b * L_ + qi * 128)) * D_ + h * HD_;
    #pragma unroll
    for (int it = 0; it < 16; it++) {
        int idx = tid + it * 256;
        int r = idx >> 5, c4 = (idx & 31) * 4;
        unsigned d = smem_u32(Qs + (size_t)r * 128 + (c4 ^ ((r & 7) << 2)));
        asm volatile("cp.async.cg.shared.global [%0], [%1], 16;\n"
                     :: "r"(d), "l"(qg + (size_t)r * D_ + c4));
    }
    attn_load_kv(K + ((size_t)(b * L_)) * KD_ + kvh * HD_,
                 V + ((size_t)(b * L_)) * KD_ + kvh * HD_, Ks, Vs, tid);
    asm volatile("cp.async.commit_group;\n");

    float m_r = -1e30f, l_r = 0.0f;
    const int myr = tid >> 1;
    const int hf  = tid & 1;

    float acc_o[2][8][4];
    #pragma unroll
    for (int i = 0; i < 2; i++)
        #pragma unroll
        for (int j = 0; j < 8; j++)
            #pragma unroll
            for (int c = 0; c < 4; c++) acc_o[i][j][c] = 0.0f;

    const float scale = 0.08838834764831845f;
    const int jmax = 2 * qi + 1;

    for (int j = 0; j <= jmax; j++) {
        const int buf = j & 1;
        asm volatile("cp.async.wait_group 0;\n");
        __syncthreads();
        if (j < jmax) {
            attn_load_kv(K + ((size_t)(b * L_ + (j + 1) * 64)) * KD_ + kvh * HD_,
                         V + ((size_t)(b * L_ + (j + 1) * 64)) * KD_ + kvh * HD_,
                         Ks + (buf ^ 1) * 8192, Vs + (buf ^ 1) * 8192, tid);
            asm volatile("cp.async.commit_group;\n");
        }

        const float* kb = Ks + buf * 8192;

        // ---- S = Q K^T (3xTF32) ----
        float sa[2][4][4];
        #pragma unroll
        for (int i = 0; i < 2; i++)
            #pragma unroll
            for (int jj = 0; jj < 4; jj++)
                #pragma unroll
                for (int c = 0; c < 4; c++) sa[i][jj][c] = 0.0f;

        #pragma unroll
        for (int ks = 0; ks < 16; ks++) {
            const int k = ks * 8;
            unsigned ah[2][4], alo[2][4], bh[4][2], bl[4][2];
            #pragma unroll
            for (int i = 0; i < 2; i++) {
                const float* p  = Qs + (size_t)(wm * 32 + i * 16 + gid) * 128;
                const float* p2 = p + 8 * 128;
                split32(p [(k + tig)     ^ swa], ah[i][0], alo[i][0]);
                split32(p2[(k + tig)     ^ swa], ah[i][1], alo[i][1]);
                split32(p [(k + tig + 4) ^ swa], ah[i][2], alo[i][2]);
                split32(p2[(k + tig + 4) ^ swa], ah[i][3], alo[i][3]);
            }
            #pragma unroll
            for (int jj = 0; jj < 4; jj++) {
                const float* p = kb + (size_t)(wn * 32 + jj * 8 + gid) * 128;
                split32(p[(k + tig)     ^ swa], bh[jj][0], bl[jj][0]);
                split32(p[(k + tig + 4) ^ swa], bh[jj][1], bl[jj][1]);
            }
            #pragma unroll
            for (int i = 0; i < 2; i++)
                #pragma unroll
                for (int jj = 0; jj < 4; jj++) {
                    MMA_TF32(sa[i][jj], ah[i][0], ah[i][1], ah[i][2], ah[i][3],
                             bl[jj][0], bl[jj][1]);
                    MMA_TF32(sa[i][jj], alo[i][0], alo[i][1], alo[i][2], alo[i][3],
                             bh[jj][0], bh[jj][1]);
                    MMA_TF32(sa[i][jj], ah[i][0], ah[i][1], ah[i][2], ah[i][3],
                             bh[jj][0], bh[jj][1]);
                }
        }

        // write S fragments to Ps
        #pragma unroll
        for (int i = 0; i < 2; i++) {
            int m0 = wm * 32 + i * 16 + gid;
            #pragma unroll
            for (int jj = 0; jj < 4; jj++) {
                int c0 = (wn * 32 + jj * 8 + tig * 2) ^ swa;
                *(float2*)&Ps[(size_t)m0 * 64 + c0] =
                    make_float2(sa[i][jj][0], sa[i][jj][1]);
                *(float2*)&Ps[(size_t)(m0 + 8) * 64 + c0] =
                    make_float2(sa[i][jj][2], sa[i][jj][3]);
            }
        }
        __syncthreads();

        // ---- softmax (thread pair per row) ----
        {
            const int r  = myr;
            const int sw = (r & 7) << 2;
            float* prow = Ps + (size_t)r * 64;
            const int gq = qi * 128 + r;
            const bool needm = (j >= 2 * qi);
            float4 vv[8];
            float tmax = -1e30f;
            #pragma unroll
            for (int q4 = 0; q4 < 8; q4++) {
                int c = hf * 32 + q4 * 4;
                float4 t = *(float4*)&prow[c ^ sw];
                t.x *= scale; t.y *= scale; t.z *= scale; t.w *= scale;
                if (needm) {
                    int gk = j * 64 + c;
                    if (gk + 0 > gq) t.x = -1e30f;
                    if (gk + 1 > gq) t.y = -1e30f;
                    if (gk + 2 > gq) t.z = -1e30f;
                    if (gk + 3 > gq) t.w = -1e30f;
                }
                vv[q4] = t;
                tmax = fmaxf(tmax, fmaxf(fmaxf(t.x, t.y), fmaxf(t.z, t.w)));
            }
            tmax = fmaxf(tmax, __shfl_xor_sync(0xffffffffu, tmax, 1));
            float mnew  = fmaxf(m_r, tmax);
            float alpha = __expf(m_r - mnew);
            float lsum = 0.0f;
            #pragma unroll
            for (int q4 = 0; q4 < 8; q4++) {
                float4 t = vv[q4];
                t.x = __expf(t.x - mnew); t.y = __expf(t.y - mnew);
                t.z = __expf(t.z - mnew); t.w = __expf(t.w - mnew);
                lsum += t.x + t.y + t.z + t.w;
                int c = hf * 32 + q4 * 4;
                *(float4*)&prow[c ^ sw] = t;
            }
            lsum += __shfl_xor_sync(0xffffffffu, lsum, 1);
            m_r = mnew;
            l_r = l_r * alpha + lsum;
            if (hf == 0) Al[r] = alpha;
        }
        __syncthreads();

        // ---- rescale O by alpha ----
        #pragma unroll
        for (int i = 0; i < 2; i++) {
            float a0 = Al[wm * 32 + i * 16 + gid];
            float a1 = Al[wm * 32 + i * 16 + 8 + gid];
            #pragma unroll
            for (int jj = 0; jj < 8; jj++) {
                acc_o[i][jj][0] *= a0; acc_o[i][jj][1] *= a0;
                acc_o[i][jj][2] *= a1; acc_o[i][jj][3] *= a1;
            }
        }

        // ---- O += P V (3xTF32) ----
        const float* vb = Vs + buf * 8192;
        #pragma unroll
        for (int ks = 0; ks < 8; ks++) {
            const int k = ks * 8;
            unsigned ah[2][4], alo[2][4];
            #pragma unroll
            for (int i = 0; i < 2; i++) {
                const float* p  = Ps + (size_t)(wm * 32 + i * 16 + gid) * 64;
                const float* p2 = p + 8 * 64;
                split32(p [(k + tig)     ^ swa], ah[i][0], alo[i][0]);
                split32(p2[(k + tig)     ^ swa], ah[i][1], alo[i][1]);
                split32(p [(k + tig + 4) ^ swa], ah[i][2], alo[i][2]);
                split32(p2[(k + tig + 4) ^ swa], ah[i][3], alo[i][3]);
            }
            #pragma unroll
            for (int half = 0; half < 2; half++) {
                unsigned bh[4][2], bl[4][2];
                #pragma unroll
                for (int jj = 0; jj < 4; jj++) {
                    int n = wn * 64 + (half * 4 + jj) * 8 + gid;
                    split32(vb[(size_t)(k + tig)     * 128 + (n ^ swv)],
                            bh[jj][0], bl[jj][0]);
                    split32(vb[(size_t)(k + tig + 4) * 128 + (n ^ swv)],
                            bh[jj][1], bl[jj][1]);
                }
                #pragma unroll
                for (int i = 0; i < 2; i++)
                    #pragma unroll
                    for (int jj = 0; jj < 4; jj++) {
                        float* d = acc_o[i][half * 4 + jj];
                        MMA_TF32(d, ah[i][0], ah[i][1], ah[i][2], ah[i][3],
                                 bl[jj][0], bl[jj][1]);
                        MMA_TF32(d, alo[i][0], alo[i][1], alo[i][2], alo[i][3],
                                 bh[jj][0], bh[jj][1]);
                        MMA_TF32(d, ah[i][0], ah[i][1], ah[i][2], ah[i][3],
                                 bh[jj][0], bh[jj][1]);
                    }
            }
        }
    }

    // ---- epilogue: normalize by 1/l and store ----
    __syncthreads();
    if (hf == 0) Al[myr] = 1.0f / l_r;
    __syncthreads();

    #pragma unroll
    for (int i = 0; i < 2; i++) {
        int m0 = wm * 32 + i * 16 + gid;
        float li0 = Al[m0], li1 = Al[m0 + 8];
        int gr = qi * 128 + m0;
        float* ob  = O + ((size_t)(b * L_) + gr) * D_ + h * HD_;
        float* ob2 = ob + (size_t)8 * D_;
        #pragma unroll
        for (int jj = 0; jj < 8; jj++) {
            int c = wn * 64 + jj * 8 + tig * 2;
            *(float2*)&ob [c] = make_float2(acc_o[i][jj][0] * li0,
                                            acc_o[i][jj][1] * li0);
            *(float2*)&ob2[c] = make_float2(acc_o[i][jj][2] * li1,
                                            acc_o[i][jj][3] * li1);
        }
    }
}

// ---------------- SiLU(gate) * up  (in place into gate) --------------------
__global__ __launch_bounds__(256) void silu_mul_kernel(
    float* __restrict__ gate, const float* __restrict__ up, int n4)
{
    int i = blockIdx.x * blockDim.x + threadIdx.x;
    if (i >= n4) return;
    float4 g = ((float4*)gate)[i];
    float4 u = ((const float4*)up)[i];
    g.x = g.x * (1.0f / (1.0f + __expf(-g.x))) * u.x;
    g.y = g.y * (1.0f / (1.0f + __expf(-g.y))) * u.y;
    g.z = g.z * (1.0f / (1.0f + __expf(-g.z))) * u.z;
    g.w = g.w * (1.0f / (1.0f + __expf(-g.w))) * u.w;
    ((float4*)gate)[i] = g;
}

// ---------------- launch ---------------------------------------------------
extern "C" void kernel_launch(void* const* d_in, const int* in_sizes, int n_in,
                              void* d_out, int out_size)
{
    (void)in_sizes; (void)n_in; (void)out_size;
    const float* x      = (const float*)d_in[0];
    const float* ln1_w  = (const float*)d_in[1];
    const float* q_w    = (const float*)d_in[2];
    const float* q_b    = (const float*)d_in[3];
    const float* k_w    = (const float*)d_in[4];
    const float* k_b    = (const float*)d_in[5];
    const float* v_w    = (const float*)d_in[6];
    const float* v_b    = (const float*)d_in[7];
    const float* o_w    = (const float*)d_in[8];
    const float* ln2_w  = (const float*)d_in[9];
    const float* gate_w = (const float*)d_in[10];
    const float* up_w   = (const float*)d_in[11];
    const float* down_w = (const float*)d_in[12];
    float* out = (float*)d_out;

    float *h, *q, *k, *v, *att, *x1, *h2, *gate, *up;
    cudaGetSymbolAddress((void**)&h,    g_h);
    cudaGetSymbolAddress((void**)&q,    g_q);
    cudaGetSymbolAddress((void**)&k,    g_k);
    cudaGetSymbolAddress((void**)&v,    g_v);
    cudaGetSymbolAddress((void**)&att,  g_att);
    cudaGetSymbolAddress((void**)&x1,   g_x1);
    cudaGetSymbolAddress((void**)&h2,   g_h2);
    cudaGetSymbolAddress((void**)&gate, g_gate);
    cudaGetSymbolAddress((void**)&up,   g_up);

    cudaFuncSetAttribute(fattn_kernel, cudaFuncAttributeMaxDynamicSharedMemorySize, ATT2_SMEM);
    cudaFuncSetAttribute(tgemm_kernel<true , false>, cudaFuncAttributeMaxDynamicSharedMemorySize, GEMM_SMEM);
    cudaFuncSetAttribute(tgemm_kernel<false, true >, cudaFuncAttributeMaxDynamicSharedMemorySize, GEMM_SMEM);
    cudaFuncSetAttribute(tgemm_kernel<false, false>, cudaFuncAttributeMaxDynamicSharedMemorySize, GEMM_SMEM);

    // 1. RMSNorm 1
    rmsnorm_kernel<<<M_, 256>>>(x, ln1_w, h);
    // 2-4. Q, K, V projections (with bias)
    tgemm_kernel<true , false><<<dim3(D_  / BN, M_ / BM), 256, GEMM_SMEM>>>(h, q_w, q_b, nullptr, q, M_, D_ , D_);
    tgemm_kernel<true , false><<<dim3(KD_ / BN, M_ / BM), 256, GEMM_SMEM>>>(h, k_w, k_b, nullptr, k, M_, KD_, D_);
    tgemm_kernel<true , false><<<dim3(KD_ / BN, M_ / BM), 256, GEMM_SMEM>>>(h, v_w, v_b, nullptr, v, M_, KD_, D_);
    // 5. causal GQA attention (tensor cores)
    fattn_kernel<<<dim3(L_ / 128, H_, B_), 256, ATT2_SMEM>>>(q, k, v, att);
    // 6. O projection + residual (x)
    tgemm_kernel<false, true ><<<dim3(D_ / BN, M_ / BM), 256, GEMM_SMEM>>>(att, o_w, nullptr, x, x1, M_, D_, D_);
    // 7. RMSNorm 2
    rmsnorm_kernel<<<M_, 256>>>(x1, ln2_w, h2);
    // 8-9. gate / up projections
    tgemm_kernel<false, false><<<dim3(F_ / BN, M_ / BM), 256, GEMM_SMEM>>>(h2, gate_w, nullptr, nullptr, gate, M_, F_, D_);
    tgemm_kernel<false, false><<<dim3(F_ / BN, M_ / BM), 256, GEMM_SMEM>>>(h2, up_w  , nullptr, nullptr, up  , M_, F_, D_);
    // 10. silu(gate) * up
    {
        int n4 = (int)((size_t)M_ * F_ / 4);
        silu_mul_kernel<<<(n4 + 255) / 256, 256>>>(gate, up, n4);
    }
    // 11. down projection + residual (x1) -> output
    tgemm_kernel<false, true ><<<dim3(D_ / BN, M_ / BM), 256, GEMM_SMEM>>>(gate, down_w, nullptr, x1, out, M_, D_, F_);
}

// round 8
// speedup vs baseline: 1.8070x; 1.0192x over previous
#include <cuda_runtime.h>
#include <math.h>

// Problem constants
#define B_   2
#define L_   2048
#define D_   2048
#define KD_  512
#define F_   5632
#define M_   (B_*L_)   // 4096 rows
#define H_   16
#define KVH_ 4
#define HD_  128

// ---------------- scratch (static device globals; no allocs allowed) -------
__device__ float g_h   [(size_t)M_ * D_];
__device__ float g_q   [(size_t)M_ * D_];
__device__ float g_k   [(size_t)M_ * KD_];
__device__ float g_v   [(size_t)M_ * KD_];
__device__ float g_att [(size_t)M_ * D_];
__device__ float g_x1  [(size_t)M_ * D_];
__device__ float g_h2  [(size_t)M_ * D_];
__device__ float g_gate[(size_t)M_ * F_];
__device__ float g_up  [(size_t)M_ * F_];

__device__ __forceinline__ unsigned smem_u32(const void* p) {
    return (unsigned)__cvta_generic_to_shared(p);
}

__device__ __forceinline__ void split32(float a, unsigned& hi, unsigned& lo) {
    unsigned h = __float_as_uint(a) & 0xffffe000u;  // truncate low 13 mantissa bits
    hi = h;
    lo = __float_as_uint(a - __uint_as_float(h));   // exact remainder
}

#define MMA_TF32(d, a0, a1, a2, a3, b0, b1)                                   \
    asm volatile(                                                             \
        "mma.sync.aligned.m16n8k8.row.col.f32.tf32.tf32.f32 "                 \
        "{%0,%1,%2,%3}, {%4,%5,%6,%7}, {%8,%9}, {%0,%1,%2,%3};\n"             \
        : "+f"(d[0]), "+f"(d[1]), "+f"(d[2]), "+f"(d[3])                      \
        : "r"(a0), "r"(a1), "r"(a2), "r"(a3), "r"(b0), "r"(b1))

// ---------------- RMSNorm: one block per row (2048 cols) -------------------
__global__ __launch_bounds__(256) void rmsnorm_kernel(
    const float* __restrict__ x, const float* __restrict__ w,
    float* __restrict__ out)
{
    int row = blockIdx.x;
    const float4* xr = (const float4*)(x + (size_t)row * D_);
    const float4* wr = (const float4*)w;
    float4* orow = (float4*)(out + (size_t)row * D_);
    int t = threadIdx.x;

    float4 v0 = xr[t];
    float4 v1 = xr[t + 256];
    float ss = v0.x*v0.x + v0.y*v0.y + v0.z*v0.z + v0.w*v0.w
             + v1.x*v1.x + v1.y*v1.y + v1.z*v1.z + v1.w*v1.w;
    #pragma unroll
    for (int o = 16; o > 0; o >>= 1) ss += __shfl_xor_sync(0xffffffffu, ss, o);

    __shared__ float red[8];
    if ((t & 31) == 0) red[t >> 5] = ss;
    __syncthreads();
    float tot = red[0] + red[1] + red[2] + red[3] + red[4] + red[5] + red[6] + red[7];
    float norm = rsqrtf(tot * (1.0f / 2048.0f) + 1e-6f);

    float4 w0 = wr[t], w1 = wr[t + 256];
    float4 r0, r1;
    r0.x = v0.x*norm*w0.x; r0.y = v0.y*norm*w0.y; r0.z = v0.z*norm*w0.z; r0.w = v0.w*norm*w0.w;
    r1.x = v1.x*norm*w1.x; r1.y = v1.y*norm*w1.y; r1.z = v1.z*norm*w1.z; r1.w = v1.w*norm*w1.w;
    orow[t] = r0;
    orow[t + 256] = r1;
}

// ================= 3xTF32 tensor-core GEMM =================================
// 128x128 block tile, BK=32, 256 threads (8 warps, each 32x64).
// __launch_bounds__(256, 2) -> <=128 regs -> 2 CTAs/SM = 4 warps/SMSP.
#define BM 128
#define BN 128
#define BK 32
#define ASTRIDE 36
#define SA_ELEMS (BM*ASTRIDE)
#define SB_ELEMS (BN*ASTRIDE)
#define GEMM_SMEM ((SA_ELEMS + SB_ELEMS) * 2 * 4)

template<bool HAS_BIAS, bool HAS_RES>
__global__ __launch_bounds__(256, 2) void tgemm_kernel(
    const float* __restrict__ A, const float* __restrict__ W,
    const float* __restrict__ bias, const float* __restrict__ res,
    float* __restrict__ C, int M, int N, int K)
{
    extern __shared__ float sm[];
    float* As = sm;                    // [2][BM][ASTRIDE]
    float* Bs = sm + 2 * SA_ELEMS;     // [2][BN][ASTRIDE]

    const int tid  = threadIdx.x;
    const int lane = tid & 31;
    const int wid  = tid >> 5;
    const int wm   = wid & 3;          // 4 row bands of 32
    const int wn   = wid >> 2;         // 2 col bands of 64
    const int gid  = lane >> 2;
    const int tig  = lane & 3;

    const int bm = blockIdx.y * BM;
    const int bn = blockIdx.x * BN;

    const int lr = tid >> 3;           // loader row 0..31
    const int lc = (tid & 7) * 4;      // loader float col 0,4,..,28

    const float* Ag = A + (size_t)(bm + lr) * K + lc;
    const float* Bg = W + (size_t)(bn + lr) * K + lc;

    float acc[2][8][4];
    #pragma unroll
    for (int i = 0; i < 2; i++)
        #pragma unroll
        for (int j = 0; j < 8; j++)
            #pragma unroll
            for (int c = 0; c < 4; c++) acc[i][j][c] = 0.0f;

    const int T = K / BK;

    {
        float* as = As;
        float* bs = Bs;
        #pragma unroll
        for (int r = 0; r < BM; r += 32) {
            unsigned dst = smem_u32(as + (size_t)(lr + r) * ASTRIDE + lc);
            asm volatile("cp.async.cg.shared.global [%0], [%1], 16;\n"
                         :: "r"(dst), "l"(Ag + (size_t)r * K));
        }
        #pragma unroll
        for (int r = 0; r < BN; r += 32) {
            unsigned dst = smem_u32(bs + (size_t)(lr + r) * ASTRIDE + lc);
            asm volatile("cp.async.cg.shared.global [%0], [%1], 16;\n"
                         :: "r"(dst), "l"(Bg + (size_t)r * K));
        }
        asm volatile("cp.async.commit_group;\n");
    }

    for (int t = 0; t < T; t++) {
        asm volatile("cp.async.wait_group 0;\n");
        __syncthreads();

        if (t + 1 < T) {
            int buf = (t + 1) & 1;
            float* as = As + buf * SA_ELEMS;
            float* bs = Bs + buf * SB_ELEMS;
            const float* ag = Ag + (size_t)(t + 1) * BK;
            const float* bg = Bg + (size_t)(t + 1) * BK;
            #pragma unroll
            for (int r = 0; r < BM; r += 32) {
                unsigned dst = smem_u32(as + (size_t)(lr + r) * ASTRIDE + lc);
                asm volatile("cp.async.cg.shared.global [%0], [%1], 16;\n"
                             :: "r"(dst), "l"(ag + (size_t)r * K));
            }
            #pragma unroll
            for (int r = 0; r < BN; r += 32) {
                unsigned dst = smem_u32(bs + (size_t)(lr + r) * ASTRIDE + lc);
                asm volatile("cp.async.cg.shared.global [%0], [%1], 16;\n"
                             :: "r"(dst), "l"(bg + (size_t)r * K));
            }
            asm volatile("cp.async.commit_group;\n");
        }

        const float* as = As + (t & 1) * SA_ELEMS;
        const float* bs = Bs + (t & 1) * SB_ELEMS;

        #pragma unroll
        for (int ks = 0; ks < 4; ks++) {
            const int k = ks * 8;
            unsigned afh[2][4], afl[2][4], bfh[8][2], bfl[8][2];
            #pragma unroll
            for (int i = 0; i < 2; i++) {
                const float* p = as + (size_t)(wm * 32 + i * 16 + gid) * ASTRIDE + k + tig;
                split32(p[0],               afh[i][0], afl[i][0]);
                split32(p[8 * ASTRIDE],     afh[i][1], afl[i][1]);
                split32(p[4],               afh[i][2], afl[i][2]);
                split32(p[8 * ASTRIDE + 4], afh[i][3], afl[i][3]);
            }
            #pragma unroll
            for (int j = 0; j < 8; j++) {
                const float* p = bs + (size_t)(wn * 64 + j * 8 + gid) * ASTRIDE + k + tig;
                split32(p[0], bfh[j][0], bfl[j][0]);
                split32(p[4], bfh[j][1], bfl[j][1]);
            }
            #pragma unroll
            for (int i = 0; i < 2; i++)
                #pragma unroll
                for (int j = 0; j < 8; j++) {
                    MMA_TF32(acc[i][j], afh[i][0], afh[i][1], afh[i][2], afh[i][3],
                             bfl[j][0], bfl[j][1]);
                    MMA_TF32(acc[i][j], afl[i][0], afl[i][1], afl[i][2], afl[i][3],
                             bfh[j][0], bfh[j][1]);
                    MMA_TF32(acc[i][j], afh[i][0], afh[i][1], afh[i][2], afh[i][3],
                             bfh[j][0], bfh[j][1]);
                }
        }
        __syncthreads();
    }

    #pragma unroll
    for (int i = 0; i < 2; i++) {
        const int r0 = bm + wm * 32 + i * 16 + gid;
        #pragma unroll
        for (int j = 0; j < 8; j++) {
            const int col = bn + wn * 64 + j * 8 + tig * 2;
            float2 v0 = make_float2(acc[i][j][0], acc[i][j][1]);
            float2 v1 = make_float2(acc[i][j][2], acc[i][j][3]);
            if (HAS_BIAS) {
                float2 bb = *(const float2*)(bias + col);
                v0.x += bb.x; v0.y += bb.y; v1.x += bb.x; v1.y += bb.y;
            }
            if (HAS_RES) {
                float2 q0 = *(const float2*)(res + (size_t)r0 * N + col);
                float2 q1 = *(const float2*)(res + (size_t)(r0 + 8) * N + col);
                v0.x += q0.x; v0.y += q0.y; v1.x += q1.x; v1.y += q1.y;
            }
            *(float2*)(C + (size_t)r0 * N + col) = v0;
            *(float2*)(C + (size_t)(r0 + 8) * N + col) = v1;
        }
    }
}

// ================= 3xTF32 tensor-core flash attention ======================
// Per CTA: 128 q rows, one (b, h). KV tiles of 64, double-buffered cp.async.
// 8 warps: wm=wid&3 (32 q-rows each), wn=wid>>2 (S: 32 kv cols; PV: 64 hd).
#define ATT2_SMEM (57472 * 4)

__device__ __forceinline__ void attn_load_kv(
    const float* kg, const float* vg, float* Ksb, float* Vsb, int tid)
{
    #pragma unroll
    for (int it = 0; it < 8; it++) {
        int idx = tid + it * 256;
        int r = idx >> 5, c4 = (idx & 31) * 4;
        unsigned kd = smem_u32(Ksb + (size_t)r * 128 + (c4 ^ ((r & 7) << 2)));
        asm volatile("cp.async.cg.shared.global [%0], [%1], 16;\n"
                     :: "r"(kd), "l"(kg + (size_t)r * KD_ + c4));
        unsigned vd = smem_u32(Vsb + (size_t)r * 128 + (c4 ^ ((r & 3) << 3)));
        asm volatile("cp.async.cg.shared.global [%0], [%1], 16;\n"
                     :: "r"(vd), "l"(vg + (size_t)r * KD_ + c4));
    }
}

__global__ __launch_bounds__(256, 1) void fattn_kernel(
    const float* __restrict__ Q, const float* __restrict__ K,
    const float* __restrict__ V, float* __restrict__ O)
{
    const int qi = (int)(gridDim.x - 1 - blockIdx.x);   // heavy diagonals first
    const int h  = blockIdx.y;
    const int b  = blockIdx.z;
    const int kvh = h & (KVH_ - 1);

    extern __shared__ float sm[];
    float* Qs = sm;              // [128][128] swizzled (col ^ (row&7)<<2)
    float* Ks = sm + 16384;      // 2 x [64][128] swizzled same
    float* Vs = sm + 32768;      // 2 x [64][128] swizzled (col ^ (row&3)<<3)
    float* Ps = sm + 49152;      // [128][64] swizzled (col ^ (row&7)<<2)
    float* Al = sm + 57344;      // [128]

    const int tid  = threadIdx.x;
    const int lane = tid & 31;
    const int wid  = tid >> 5;
    const int wm   = wid & 3;
    const int wn   = wid >> 2;
    const int gid  = lane >> 2;
    const int tig  = lane & 3;
    const int swa  = gid << 2;   // A/B fragment row swizzle (row&7 == gid)
    const int swv  = tig << 3;   // V fragment row swizzle (row&3 == tig)

    // ---- Q tile load (once) ----
    const float* qg = Q + ((size_t)(b * L_ + qi * 128)) * D_ + h * HD_;
    #pragma unroll
    for (int it = 0; it < 16; it++) {
        int idx = tid + it * 256;
        int r = idx >> 5, c4 = (idx & 31) * 4;
        unsigned d = smem_u32(Qs + (size_t)r * 128 + (c4 ^ ((r & 7) << 2)));
        asm volatile("cp.async.cg.shared.global [%0], [%1], 16;\n"
                     :: "r"(d), "l"(qg + (size_t)r * D_ + c4));
    }
    attn_load_kv(K + ((size_t)(b * L_)) * KD_ + kvh * HD_,
                 V + ((size_t)(b * L_)) * KD_ + kvh * HD_, Ks, Vs, tid);
    asm volatile("cp.async.commit_group;\n");

    float m_r = -1e30f, l_r = 0.0f;
    const int myr = tid >> 1;
    const int hf  = tid & 1;

    float acc_o[2][8][4];
    #pragma unroll
    for (int i = 0; i < 2; i++)
        #pragma unroll
        for (int j = 0; j < 8; j++)
            #pragma unroll
            for (int c = 0; c < 4; c++) acc_o[i][j][c] = 0.0f;

    const float scale = 0.08838834764831845f;
    const int jmax = 2 * qi + 1;

    for (int j = 0; j <= jmax; j++) {
        const int buf = j & 1;
        asm volatile("cp.async.wait_group 0;\n");
        __syncthreads();
        if (j < jmax) {
            attn_load_kv(K + ((size_t)(b * L_ + (j + 1) * 64)) * KD_ + kvh * HD_,
                         V + ((size_t)(b * L_ + (j + 1) * 64)) * KD_ + kvh * HD_,
                         Ks + (buf ^ 1) * 8192, Vs + (buf ^ 1) * 8192, tid);
            asm volatile("cp.async.commit_group;\n");
        }

        const float* kb = Ks + buf * 8192;

        // ---- S = Q K^T (3xTF32) ----
        float sa[2][4][4];
        #pragma unroll
        for (int i = 0; i < 2; i++)
            #pragma unroll
            for (int jj = 0; jj < 4; jj++)
                #pragma unroll
                for (int c = 0; c < 4; c++) sa[i][jj][c] = 0.0f;

        #pragma unroll
        for (int ks = 0; ks < 16; ks++) {
            const int k = ks * 8;
            unsigned ah[2][4], alo[2][4], bh[4][2], bl[4][2];
            #pragma unroll
            for (int i = 0; i < 2; i++) {
                const float* p  = Qs + (size_t)(wm * 32 + i * 16 + gid) * 128;
                const float* p2 = p + 8 * 128;
                split32(p [(k + tig)     ^ swa], ah[i][0], alo[i][0]);
                split32(p2[(k + tig)     ^ swa], ah[i][1], alo[i][1]);
                split32(p [(k + tig + 4) ^ swa], ah[i][2], alo[i][2]);
                split32(p2[(k + tig + 4) ^ swa], ah[i][3], alo[i][3]);
            }
            #pragma unroll
            for (int jj = 0; jj < 4; jj++) {
                const float* p = kb + (size_t)(wn * 32 + jj * 8 + gid) * 128;
                split32(p[(k + tig)     ^ swa], bh[jj][0], bl[jj][0]);
                split32(p[(k + tig + 4) ^ swa], bh[jj][1], bl[jj][1]);
            }
            #pragma unroll
            for (int i = 0; i < 2; i++)
                #pragma unroll
                for (int jj = 0; jj < 4; jj++) {
                    MMA_TF32(sa[i][jj], ah[i][0], ah[i][1], ah[i][2], ah[i][3],
                             bl[jj][0], bl[jj][1]);
                    MMA_TF32(sa[i][jj], alo[i][0], alo[i][1], alo[i][2], alo[i][3],
                             bh[jj][0], bh[jj][1]);
                    MMA_TF32(sa[i][jj], ah[i][0], ah[i][1], ah[i][2], ah[i][3],
                             bh[jj][0], bh[jj][1]);
                }
        }

        // write S fragments to Ps
        #pragma unroll
        for (int i = 0; i < 2; i++) {
            int m0 = wm * 32 + i * 16 + gid;
            #pragma unroll
            for (int jj = 0; jj < 4; jj++) {
                int c0 = (wn * 32 + jj * 8 + tig * 2) ^ swa;
                *(float2*)&Ps[(size_t)m0 * 64 + c0] =
                    make_float2(sa[i][jj][0], sa[i][jj][1]);
                *(float2*)&Ps[(size_t)(m0 + 8) * 64 + c0] =
                    make_float2(sa[i][jj][2], sa[i][jj][3]);
            }
        }
        __syncthreads();

        // ---- softmax (thread pair per row) ----
        {
            const int r  = myr;
            const int sw = (r & 7) << 2;
            float* prow = Ps + (size_t)r * 64;
            const int gq = qi * 128 + r;
            const bool needm = (j >= 2 * qi);
            float4 vv[8];
            float tmax = -1e30f;
            #pragma unroll
            for (int q4 = 0; q4 < 8; q4++) {
                int c = hf * 32 + q4 * 4;
                float4 t = *(float4*)&prow[c ^ sw];
                t.x *= scale; t.y *= scale; t.z *= scale; t.w *= scale;
                if (needm) {
                    int gk = j * 64 + c;
                    if (gk + 0 > gq) t.x = -1e30f;
                    if (gk + 1 > gq) t.y = -1e30f;
                    if (gk + 2 > gq) t.z = -1e30f;
                    if (gk + 3 > gq) t.w = -1e30f;
                }
                vv[q4] = t;
                tmax = fmaxf(tmax, fmaxf(fmaxf(t.x, t.y), fmaxf(t.z, t.w)));
            }
            tmax = fmaxf(tmax, __shfl_xor_sync(0xffffffffu, tmax, 1));
            float mnew  = fmaxf(m_r, tmax);
            float alpha = __expf(m_r - mnew);
            float lsum = 0.0f;
            #pragma unroll
            for (int q4 = 0; q4 < 8; q4++) {
                float4 t = vv[q4];
                t.x = __expf(t.x - mnew); t.y = __expf(t.y - mnew);
                t.z = __expf(t.z - mnew); t.w = __expf(t.w - mnew);
                lsum += t.x + t.y + t.z + t.w;
                int c = hf * 32 + q4 * 4;
                *(float4*)&prow[c ^ sw] = t;
            }
            lsum += __shfl_xor_sync(0xffffffffu, lsum, 1);
            m_r = mnew;
            l_r = l_r * alpha + lsum;
            if (hf == 0) Al[r] = alpha;
        }
        __syncthreads();

        // ---- rescale O by alpha ----
        #pragma unroll
        for (int i = 0; i < 2; i++) {
            float a0 = Al[wm * 32 + i * 16 + gid];
            float a1 = Al[wm * 32 + i * 16 + 8 + gid];
            #pragma unroll
            for (int jj = 0; jj < 8; jj++) {
                acc_o[i][jj][0] *= a0; acc_o[i][jj][1] *= a0;
                acc_o[i][jj][2] *= a1; acc_o[i][jj][3] *= a1;
            }
        }

        // ---- O += P V (3xTF32) ----
        const float* vb = Vs + buf * 8192;
        #pragma unroll
        for (int ks = 0; ks < 8; ks++) {
            const int k = ks * 8;
            unsigned ah[2][4], alo[2][4];
            #pragma unroll
            for (int i = 0; i < 2; i++) {
                const float* p  = Ps + (size_t)(wm * 32 + i * 16 + gid) * 64;
                const float* p2 = p + 8 * 64;
                split32(p [(k + tig)     ^ swa], ah[i][0], alo[i][0]);
                split32(p2[(k + tig)     ^ swa], ah[i][1], alo[i][1]);
                split32(p [(k + tig + 4) ^ swa], ah[i][2], alo[i][2]);
                split32(p2[(k + tig + 4) ^ swa], ah[i][3], alo[i][3]);
            }
            #pragma unroll
            for (int half = 0; half < 2; half++) {
                unsigned bh[4][2], bl[4][2];
                #pragma unroll
                for (int jj = 0; jj < 4; jj++) {
                    int n = wn * 64 + (half * 4 + jj) * 8 + gid;
                    split32(vb[(size_t)(k + tig)     * 128 + (n ^ swv)],
                            bh[jj][0], bl[jj][0]);
                    split32(vb[(size_t)(k + tig + 4) * 128 + (n ^ swv)],
                            bh[jj][1], bl[jj][1]);
                }
                #pragma unroll
                for (int i = 0; i < 2; i++)
                    #pragma unroll
                    for (int jj = 0; jj < 4; jj++) {
                        float* d = acc_o[i][half * 4 + jj];
                        MMA_TF32(d, ah[i][0], ah[i][1], ah[i][2], ah[i][3],
                                 bl[jj][0], bl[jj][1]);
                        MMA_TF32(d, alo[i][0], alo[i][1], alo[i][2], alo[i][3],
                                 bh[jj][0], bh[jj][1]);
                        MMA_TF32(d, ah[i][0], ah[i][1], ah[i][2], ah[i][3],
                                 bh[jj][0], bh[jj][1]);
                    }
            }
        }
    }

    // ---- epilogue: normalize by 1/l and store ----
    __syncthreads();
    if (hf == 0) Al[myr] = 1.0f / l_r;
    __syncthreads();

    #pragma unroll
    for (int i = 0; i < 2; i++) {
        int m0 = wm * 32 + i * 16 + gid;
        float li0 = Al[m0], li1 = Al[m0 + 8];
        int gr = qi * 128 + m0;
        float* ob  = O + ((size_t)(b * L_) + gr) * D_ + h * HD_;
        float* ob2 = ob + (size_t)8 * D_;
        #pragma unroll
        for (int jj = 0; jj < 8; jj++) {
            int c = wn * 64 + jj * 8 + tig * 2;
            *(float2*)&ob [c] = make_float2(acc_o[i][jj][0] * li0,
                                            acc_o[i][jj][1] * li0);
            *(float2*)&ob2[c] = make_float2(acc_o[i][jj][2] * li1,
                                            acc_o[i][jj][3] * li1);
        }
    }
}

// ---------------- SiLU(gate) * up  (in place into gate) --------------------
__global__ __launch_bounds__(256) void silu_mul_kernel(
    float* __restrict__ gate, const float* __restrict__ up, int n4)
{
    int i = blockIdx.x * blockDim.x + threadIdx.x;
    if (i >= n4) return;
    float4 g = ((float4*)gate)[i];
    float4 u = ((const float4*)up)[i];
    g.x = g.x * (1.0f / (1.0f + __expf(-g.x))) * u.x;
    g.y = g.y * (1.0f / (1.0f + __expf(-g.y))) * u.y;
    g.z = g.z * (1.0f / (1.0f + __expf(-g.z))) * u.z;
    g.w = g.w * (1.0f / (1.0f + __expf(-g.w))) * u.w;
    ((float4*)gate)[i] = g;
}

// ---------------- launch ---------------------------------------------------
extern "C" void kernel_launch(void* const* d_in, const int* in_sizes, int n_in,
                              void* d_out, int out_size)
{
    (void)in_sizes; (void)n_in; (void)out_size;
    const float* x      = (const float*)d_in[0];
    const float* ln1_w  = (const float*)d_in[1];
    const float* q_w    = (const float*)d_in[2];
    const float* q_b    = (const float*)d_in[3];
    const float* k_w    = (const float*)d_in[4];
    const float* k_b    = (const float*)d_in[5];
    const float* v_w    = (const float*)d_in[6];
    const float* v_b    = (const float*)d_in[7];
    const float* o_w    = (const float*)d_in[8];
    const float* ln2_w  = (const float*)d_in[9];
    const float* gate_w = (const float*)d_in[10];
    const float* up_w   = (const float*)d_in[11];
    const float* down_w = (const float*)d_in[12];
    float* out = (float*)d_out;

    float *h, *q, *k, *v, *att, *x1, *h2, *gate, *up;
    cudaGetSymbolAddress((void**)&h,    g_h);
    cudaGetSymbolAddress((void**)&q,    g_q);
    cudaGetSymbolAddress((void**)&k,    g_k);
    cudaGetSymbolAddress((void**)&v,    g_v);
    cudaGetSymbolAddress((void**)&att,  g_att);
    cudaGetSymbolAddress((void**)&x1,   g_x1);
    cudaGetSymbolAddress((void**)&h2,   g_h2);
    cudaGetSymbolAddress((void**)&gate, g_gate);
    cudaGetSymbolAddress((void**)&up,   g_up);

    cudaFuncSetAttribute(fattn_kernel, cudaFuncAttributeMaxDynamicSharedMemorySize, ATT2_SMEM);
    cudaFuncSetAttribute(tgemm_kernel<true , false>, cudaFuncAttributeMaxDynamicSharedMemorySize, GEMM_SMEM);
    cudaFuncSetAttribute(tgemm_kernel<false, true >, cudaFuncAttributeMaxDynamicSharedMemorySize, GEMM_SMEM);
    cudaFuncSetAttribute(tgemm_kernel<false, false>, cudaFuncAttributeMaxDynamicSharedMemorySize, GEMM_SMEM);

    // 1. RMSNorm 1
    rmsnorm_kernel<<<M_, 256>>>(x, ln1_w, h);
    // 2-4. Q, K, V projections (with bias)
    tgemm_kernel<true , false><<<dim3(D_  / BN, M_ / BM), 256, GEMM_SMEM>>>(h, q_w, q_b, nullptr, q, M_, D_ , D_);
    tgemm_kernel<true , false><<<dim3(KD_ / BN, M_ / BM), 256, GEMM_SMEM>>>(h, k_w, k_b, nullptr, k, M_, KD_, D_);
    tgemm_kernel<true , false><<<dim3(KD_ / BN, M_ / BM), 256, GEMM_SMEM>>>(h, v_w, v_b, nullptr, v, M_, KD_, D_);
    // 5. causal GQA attention (tensor cores)
    fattn_kernel<<<dim3(L_ / 128, H_, B_), 256, ATT2_SMEM>>>(q, k, v, att);
    // 6. O projection + residual (x)
    tgemm_kernel<false, true ><<<dim3(D_ / BN, M_ / BM), 256, GEMM_SMEM>>>(att, o_w, nullptr, x, x1, M_, D_, D_);
    // 7. RMSNorm 2
    rmsnorm_kernel<<<M_, 256>>>(x1, ln2_w, h2);
    // 8-9. gate / up projections
    tgemm_kernel<false, false><<<dim3(F_ / BN, M_ / BM), 256, GEMM_SMEM>>>(h2, gate_w, nullptr, nullptr, gate, M_, F_, D_);
    tgemm_kernel<false, false><<<dim3(F_ / BN, M_ / BM), 256, GEMM_SMEM>>>(h2, up_w  , nullptr, nullptr, up  , M_, F_, D_);
    // 10. silu(gate) * up
    {
        int n4 = (int)((size_t)M_ * F_ / 4);
        silu_mul_kernel<<<(n4 + 255) / 256, 256>>>(gate, up, n4);
    }
    // 11. down projection + residual (x1) -> output
    tgemm_kernel<false, true ><<<dim3(D_ / BN, M_ / BM), 256, GEMM_SMEM>>>(gate, down_w, nullptr, x1, out, M_, D_, F_);
}

// round 10
// speedup vs baseline: 2.5304x; 1.4003x over previous
#include <cuda_runtime.h>
#include <cuda_bf16.h>
#include <math.h>

// Problem constants
#define B_   2
#define L_   2048
#define D_   2048
#define KD_  512
#define F_   5632
#define M_   (B_*L_)   // 4096 rows
#define H_   16
#define KVH_ 4
#define HD_  128

// ---------------- scratch (static device globals; no allocs allowed) -------
// fp32 intermediates
__device__ float g_q   [(size_t)M_ * D_];
__device__ float g_k   [(size_t)M_ * KD_];
__device__ float g_v   [(size_t)M_ * KD_];
__device__ float g_att [(size_t)M_ * D_];
__device__ float g_x1  [(size_t)M_ * D_];
__device__ float g_gate[(size_t)M_ * F_];
__device__ float g_up  [(size_t)M_ * F_];
// bf16x2-split operands (tiled: per 32-k block, 32 hi then 32 lo bf16)
__device__ __nv_bfloat16 g_hs [(size_t)M_  * 2 * D_];
__device__ __nv_bfloat16 g_as [(size_t)M_  * 2 * D_];
__device__ __nv_bfloat16 g_h2s[(size_t)M_  * 2 * D_];
__device__ __nv_bfloat16 g_gs [(size_t)M_  * 2 * F_];
__device__ __nv_bfloat16 g_qws[(size_t)D_  * 2 * D_];
__device__ __nv_bfloat16 g_kws[(size_t)KD_ * 2 * D_];
__device__ __nv_bfloat16 g_vws[(size_t)KD_ * 2 * D_];
__device__ __nv_bfloat16 g_ows[(size_t)D_  * 2 * D_];
__device__ __nv_bfloat16 g_gws[(size_t)F_  * 2 * D_];
__device__ __nv_bfloat16 g_uws[(size_t)F_  * 2 * D_];
__device__ __nv_bfloat16 g_dws[(size_t)D_  * 2 * F_];

__device__ __forceinline__ unsigned smem_u32(const void* p) {
    return (unsigned)__cvta_generic_to_shared(p);
}

// Dekker-style bf16x2 split of two adjacent values, packed (low 16 = first k)
__device__ __forceinline__ void split2(float a, float b, unsigned& hi, unsigned& lo) {
    __nv_bfloat16 ha = __float2bfloat16(a), hb = __float2bfloat16(b);
    float ra = a - __bfloat162float(ha);
    float rb = b - __bfloat162float(hb);
    __nv_bfloat16 la = __float2bfloat16(ra), lb = __float2bfloat16(rb);
    hi = ((unsigned)__bfloat16_as_ushort(hb) << 16) | __bfloat16_as_ushort(ha);
    lo = ((unsigned)__bfloat16_as_ushort(lb) << 16) | __bfloat16_as_ushort(la);
}

__device__ __forceinline__ void split32(float a, unsigned& hi, unsigned& lo) {
    unsigned h = __float_as_uint(a) & 0xffffe000u;
    hi = h;
    lo = __float_as_uint(a - __uint_as_float(h));
}

#define MMA_TF32(d, a0, a1, a2, a3, b0, b1)                                   \
    asm volatile(                                                             \
        "mma.sync.aligned.m16n8k8.row.col.f32.tf32.tf32.f32 "                 \
        "{%0,%1,%2,%3}, {%4,%5,%6,%7}, {%8,%9}, {%0,%1,%2,%3};\n"             \
        : "+f"(d[0]), "+f"(d[1]), "+f"(d[2]), "+f"(d[3])                      \
        : "r"(a0), "r"(a1), "r"(a2), "r"(a3), "r"(b0), "r"(b1))

#define MMA_BF16(d, a0, a1, a2, a3, b0, b1)                                   \
    asm volatile(                                                             \
        "mma.sync.aligned.m16n8k16.row.col.f32.bf16.bf16.f32 "                \
        "{%0,%1,%2,%3}, {%4,%5,%6,%7}, {%8,%9}, {%0,%1,%2,%3};\n"             \
        : "+f"(d[0]), "+f"(d[1]), "+f"(d[2]), "+f"(d[3])                      \
        : "r"(a0), "r"(a1), "r"(a2), "r"(a3), "r"(b0), "r"(b1))

// swizzled smem read: row r (128B rows), 16B chunk ch, byte offset w in chunk
#define LDSW(base, r, ch, w) \
    (*(const unsigned*)((base) + (size_t)(r) * 128 + ((((ch) ^ ((r) & 7))) << 4) + (w)))

// ---------------- split kernels --------------------------------------------
// generic: fp32 [N][K] row-major -> tiled bf16x2 [N][2K]
__global__ __launch_bounds__(256) void split_kernel(
    const float* __restrict__ in, __nv_bfloat16* __restrict__ out, int K)
{
    int k2 = blockIdx.x * 256 + threadIdx.x;
    if (2 * k2 >= K) return;
    size_t n = blockIdx.y;
    float2 v = *(const float2*)(in + n * (size_t)K + 2 * k2);
    unsigned hi, lo; split2(v.x, v.y, hi, lo);
    int k = 2 * k2, blk = k >> 5, pos = k & 31;
    __nv_bfloat16* o = out + n * (size_t)(2 * K) + blk * 64 + pos;
    *(unsigned*)o        = hi;
    *(unsigned*)(o + 32) = lo;
}

__device__ __forceinline__ void write_split4(__nv_bfloat16* rowbase, int c, float4 v) {
    int blk = c >> 5, pos = c & 31;
    __nv_bfloat16* o = rowbase + blk * 64 + pos;
    unsigned h0, l0, h1, l1;
    split2(v.x, v.y, h0, l0);
    split2(v.z, v.w, h1, l1);
    *(unsigned*)(o)      = h0; *(unsigned*)(o + 2)  = h1;
    *(unsigned*)(o + 32) = l0; *(unsigned*)(o + 34) = l1;
}

// ---------------- RMSNorm -> split output ----------------------------------
__global__ __launch_bounds__(256) void rmsnorm_split_kernel(
    const float* __restrict__ x, const float* __restrict__ w,
    __nv_bfloat16* __restrict__ outs)
{
    int row = blockIdx.x;
    const float4* xr = (const float4*)(x + (size_t)row * D_);
    const float4* wr = (const float4*)w;
    int t = threadIdx.x;

    float4 v0 = xr[t];
    float4 v1 = xr[t + 256];
    float ss = v0.x*v0.x + v0.y*v0.y + v0.z*v0.z + v0.w*v0.w
             + v1.x*v1.x + v1.y*v1.y + v1.z*v1.z + v1.w*v1.w;
    #pragma unroll
    for (int o = 16; o > 0; o >>= 1) ss += __shfl_xor_sync(0xffffffffu, ss, o);

    __shared__ float red[8];
    if ((t & 31) == 0) red[t >> 5] = ss;
    __syncthreads();
    float tot = red[0] + red[1] + red[2] + red[3] + red[4] + red[5] + red[6] + red[7];
    float norm = rsqrtf(tot * (1.0f / 2048.0f) + 1e-6f);

    float4 w0 = wr[t], w1 = wr[t + 256];
    float4 r0, r1;
    r0.x = v0.x*norm*w0.x; r0.y = v0.y*norm*w0.y; r0.z = v0.z*norm*w0.z; r0.w = v0.w*norm*w0.w;
    r1.x = v1.x*norm*w1.x; r1.y = v1.y*norm*w1.y; r1.z = v1.z*norm*w1.z; r1.w = v1.w*norm*w1.w;

    __nv_bfloat16* rowbase = outs + (size_t)row * (2 * D_);
    write_split4(rowbase, t * 4, r0);
    write_split4(rowbase, (t + 256) * 4, r1);
}

// ---------------- SiLU(gate)*up -> split output ----------------------------
__global__ __launch_bounds__(256) void silu_mul_split_kernel(
    const float* __restrict__ gate, const float* __restrict__ up,
    __nv_bfloat16* __restrict__ outs)
{
    int k2 = blockIdx.x * 256 + threadIdx.x;     // 0..2815
    size_t n = blockIdx.y;
    float2 g = *(const float2*)(gate + n * (size_t)F_ + 2 * k2);
    float2 u = *(const float2*)(up   + n * (size_t)F_ + 2 * k2);
    g.x = g.x * (1.0f / (1.0f + __expf(-g.x))) * u.x;
    g.y = g.y * (1.0f / (1.0f + __expf(-g.y))) * u.y;
    unsigned hi, lo; split2(g.x, g.y, hi, lo);
    int k = 2 * k2, blk = k >> 5, pos = k & 31;
    __nv_bfloat16* o = outs + n * (size_t)(2 * F_) + blk * 64 + pos;
    *(unsigned*)o        = hi;
    *(unsigned*)(o + 32) = lo;
}

// ================= bf16x2 tensor-core GEMM =================================
// C[M,N] = A[M,K] @ W[N,K]^T (+bias)(+res), operands pre-split bf16x2 tiled.
// 128x128 tile, BK=32, 256 thr (8 warps, 32x64 each). 3x m16n8k16 bf16 MMA:
// ah*bl + al*bh + ah*bh. smem rows: 128B = [32 hi | 32 lo] bf16, 16B-XOR swz.
#define BM 128
#define BN 128
#define GEMM_SMEM (4 * 16384)

template<bool HAS_BIAS, bool HAS_RES>
__global__ __launch_bounds__(256, 2) void bgemm_kernel(
    const __nv_bfloat16* __restrict__ A, const __nv_bfloat16* __restrict__ Wt,
    const float* __restrict__ bias, const float* __restrict__ res,
    float* __restrict__ C, int M, int N, int K)
{
    extern __shared__ char smc[];
    char* As = smc;             // 2 x 16KB
    char* Bs = smc + 32768;     // 2 x 16KB

    const int tid  = threadIdx.x;
    const int lane = tid & 31;
    const int wid  = tid >> 5;
    const int wm   = wid & 3;
    const int wn   = wid >> 2;
    const int gid  = lane >> 2;
    const int tig  = lane & 3;

    const int bm = blockIdx.y * BM;
    const int bn = blockIdx.x * BN;

    const int lr  = tid >> 1;          // 0..127
    const int lcb = (tid & 1) * 4;     // chunk base 0 or 4

    const size_t rowb = (size_t)4 * K; // bytes per split row (2K bf16)
    const char* Ag = (const char*)A  + (size_t)(bm + lr) * rowb;
    const char* Bg = (const char*)Wt + (size_t)(bn + lr) * rowb;

    float acc[2][8][4];
    #pragma unroll
    for (int i = 0; i < 2; i++)
        #pragma unroll
        for (int j = 0; j < 8; j++)
            #pragma unroll
            for (int c = 0; c < 4; c++) acc[i][j][c] = 0.0f;

    const int T = K / 32;
    const int swr = lr & 7;

    // prefetch tile 0
    {
        char* a = As; char* b = Bs;
        #pragma unroll
        for (int c = 0; c < 4; c++) {
            int ch = lcb + c, dch = ch ^ swr;
            unsigned da = smem_u32(a + (size_t)lr * 128 + dch * 16);
            asm volatile("cp.async.cg.shared.global [%0], [%1], 16;\n"
                         :: "r"(da), "l"(Ag + ch * 16));
            unsigned db = smem_u32(b + (size_t)lr * 128 + dch * 16);
            asm volatile("cp.async.cg.shared.global [%0], [%1], 16;\n"
                         :: "r"(db), "l"(Bg + ch * 16));
        }
        asm volatile("cp.async.commit_group;\n");
    }

    for (int t = 0; t < T; t++) {
        asm volatile("cp.async.wait_group 0;\n");
        __syncthreads();

        if (t + 1 < T) {
            int buf = (t + 1) & 1;
            char* a = As + buf * 16384;
            char* b = Bs + buf * 16384;
            const char* ag = Ag + (size_t)(t + 1) * 128;
            const char* bg = Bg + (size_t)(t + 1) * 128;
            #pragma unroll
            for (int c = 0; c < 4; c++) {
                int ch = lcb + c, dch = ch ^ swr;
                unsigned da = smem_u32(a + (size_t)lr * 128 + dch * 16);
                asm volatile("cp.async.cg.shared.global [%0], [%1], 16;\n"
                             :: "r"(da), "l"(ag + ch * 16));
                unsigned db = smem_u32(b + (size_t)lr * 128 + dch * 16);
                asm volatile("cp.async.cg.shared.global [%0], [%1], 16;\n"
                             :: "r"(db), "l"(bg + ch * 16));
            }
            asm volatile("cp.async.commit_group;\n");
        }

        const char* a = As + (t & 1) * 16384;
        const char* b = Bs + (t & 1) * 16384;

        #pragma unroll
        for (int ks = 0; ks < 2; ks++) {
            const int c0 = 2 * ks;        // hi chunks: c0, c0+1; lo: c0+4, c0+5
            const int w4 = tig * 4;
            unsigned ah[2][4], al_[2][4];
            #pragma unroll
            for (int i = 0; i < 2; i++) {
                int r = wm * 32 + i * 16 + gid;
                ah[i][0]  = LDSW(a, r,     c0,     w4);
                ah[i][1]  = LDSW(a, r + 8, c0,     w4);
                ah[i][2]  = LDSW(a, r,     c0 + 1, w4);
                ah[i][3]  = LDSW(a, r + 8, c0 + 1, w4);
                al_[i][0] = LDSW(a, r,     c0 + 4, w4);
                al_[i][1] = LDSW(a, r + 8, c0 + 4, w4);
                al_[i][2] = LDSW(a, r,     c0 + 5, w4);
                al_[i][3] = LDSW(a, r + 8, c0 + 5, w4);
            }
            unsigned bh[8][2], bl[8][2];
            #pragma unroll
            for (int j = 0; j < 8; j++) {
                int n = wn * 64 + j * 8 + gid;
                bh[j][0] = LDSW(b, n, c0,     w4);
                bh[j][1] = LDSW(b, n, c0 + 1, w4);
                bl[j][0] = LDSW(b, n, c0 + 4, w4);
                bl[j][1] = LDSW(b, n, c0 + 5, w4);
            }
            #pragma unroll
            for (int i = 0; i < 2; i++)
                #pragma unroll
                for (int j = 0; j < 8; j++) {
                    MMA_BF16(acc[i][j], ah[i][0], ah[i][1], ah[i][2], ah[i][3],
                             bl[j][0], bl[j][1]);
                    MMA_BF16(acc[i][j], al_[i][0], al_[i][1], al_[i][2], al_[i][3],
                             bh[j][0], bh[j][1]);
                    MMA_BF16(acc[i][j], ah[i][0], ah[i][1], ah[i][2], ah[i][3],
                             bh[j][0], bh[j][1]);
                }
        }
        __syncthreads();
    }

    #pragma unroll
    for (int i = 0; i < 2; i++) {
        const int r0 = bm + wm * 32 + i * 16 + gid;
        #pragma unroll
        for (int j = 0; j < 8; j++) {
            const int col = bn + wn * 64 + j * 8 + tig * 2;
            float2 v0 = make_float2(acc[i][j][0], acc[i][j][1]);
            float2 v1 = make_float2(acc[i][j][2], acc[i][j][3]);
            if (HAS_BIAS) {
                float2 bb = *(const float2*)(bias + col);
                v0.x += bb.x; v0.y += bb.y; v1.x += bb.x; v1.y += bb.y;
            }
            if (HAS_RES) {
                float2 q0 = *(const float2*)(res + (size_t)r0 * N + col);
                float2 q1 = *(const float2*)(res + (size_t)(r0 + 8) * N + col);
                v0.x += q0.x; v0.y += q0.y; v1.x += q1.x; v1.y += q1.y;
            }
            *(float2*)(C + (size_t)r0 * N + col) = v0;
            *(float2*)(C + (size_t)(r0 + 8) * N + col) = v1;
        }
    }
}

// ================= 3xTF32 tensor-core flash attention (unchanged) ==========
#define ATT2_SMEM (57472 * 4)

__device__ __forceinline__ void attn_load_kv(
    const float* kg, const float* vg, float* Ksb, float* Vsb, int tid)
{
    #pragma unroll
    for (int it = 0; it < 8; it++) {
        int idx = tid + it * 256;
        int r = idx >> 5, c4 = (idx & 31) * 4;
        unsigned kd = smem_u32(Ksb + (size_t)r * 128 + (c4 ^ ((r & 7) << 2)));
        asm volatile("cp.async.cg.shared.global [%0], [%1], 16;\n"
                     :: "r"(kd), "l"(kg + (size_t)r * KD_ + c4));
        unsigned vd = smem_u32(Vsb + (size_t)r * 128 + (c4 ^ ((r & 3) << 3)));
        asm volatile("cp.async.cg.shared.global [%0], [%1], 16;\n"
                     :: "r"(vd), "l"(vg + (size_t)r * KD_ + c4));
    }
}

__global__ __launch_bounds__(256, 1) void fattn_kernel(
    const float* __restrict__ Q, const float* __restrict__ K,
    const float* __restrict__ V, float* __restrict__ O)
{
    const int qi = (int)(gridDim.x - 1 - blockIdx.x);
    const int h  = blockIdx.y;
    const int b  = blockIdx.z;
    const int kvh = h & (KVH_ - 1);

    extern __shared__ float sm[];
    float* Qs = sm;
    float* Ks = sm + 16384;
    float* Vs = sm + 32768;
    float* Ps = sm + 49152;
    float* Al = sm + 57344;

    const int tid  = threadIdx.x;
    const int lane = tid & 31;
    const int wid  = tid >> 5;
    const int wm   = wid & 3;
    const int wn   = wid >> 2;
    const int gid  = lane >> 2;
    const int tig  = lane & 3;
    const int swa  = gid << 2;
    const int swv  = tig << 3;

    const float* qg = Q + ((size_t)(b * L_ + qi * 128)) * D_ + h * HD_;
    #pragma unroll
    for (int it = 0; it < 16; it++) {
        int idx = tid + it * 256;
        int r = idx >> 5, c4 = (idx & 31) * 4;
        unsigned d = smem_u32(Qs + (size_t)r * 128 + (c4 ^ ((r & 7) << 2)));
        asm volatile("cp.async.cg.shared.global [%0], [%1], 16;\n"
                     :: "r"(d), "l"(qg + (size_t)r * D_ + c4));
    }
    attn_load_kv(K + ((size_t)(b * L_)) * KD_ + kvh * HD_,
                 V + ((size_t)(b * L_)) * KD_ + kvh * HD_, Ks, Vs, tid);
    asm volatile("cp.async.commit_group;\n");

    float m_r = -1e30f, l_r = 0.0f;
    const int myr = tid >> 1;
    const int hf  = tid & 1;

    float acc_o[2][8][4];
    #pragma unroll
    for (int i = 0; i < 2; i++)
        #pragma unroll
        for (int j = 0; j < 8; j++)
            #pragma unroll
            for (int c = 0; c < 4; c++) acc_o[i][j][c] = 0.0f;

    const float scale = 0.08838834764831845f;
    const int jmax = 2 * qi + 1;

    for (int j = 0; j <= jmax; j++) {
        const int buf = j & 1;
        asm volatile("cp.async.wait_group 0;\n");
        __syncthreads();
        if (j < jmax) {
            attn_load_kv(K + ((size_t)(b * L_ + (j + 1) * 64)) * KD_ + kvh * HD_,
                         V + ((size_t)(b * L_ + (j + 1) * 64)) * KD_ + kvh * HD_,
                         Ks + (buf ^ 1) * 8192, Vs + (buf ^ 1) * 8192, tid);
            asm volatile("cp.async.commit_group;\n");
        }

        const float* kb = Ks + buf * 8192;

        float sa[2][4][4];
        #pragma unroll
        for (int i = 0; i < 2; i++)
            #pragma unroll
            for (int jj = 0; jj < 4; jj++)
                #pragma unroll
                for (int c = 0; c < 4; c++) sa[i][jj][c] = 0.0f;

        #pragma unroll
        for (int ks = 0; ks < 16; ks++) {
            const int k = ks * 8;
            unsigned ah[2][4], alo[2][4], bh[4][2], bl[4][2];
            #pragma unroll
            for (int i = 0; i < 2; i++) {
                const float* p  = Qs + (size_t)(wm * 32 + i * 16 + gid) * 128;
                const float* p2 = p + 8 * 128;
                split32(p [(k + tig)     ^ swa], ah[i][0], alo[i][0]);
                split32(p2[(k + tig)     ^ swa], ah[i][1], alo[i][1]);
                split32(p [(k + tig + 4) ^ swa], ah[i][2], alo[i][2]);
                split32(p2[(k + tig + 4) ^ swa], ah[i][3], alo[i][3]);
            }
            #pragma unroll
            for (int jj = 0; jj < 4; jj++) {
                const float* p = kb + (size_t)(wn * 32 + jj * 8 + gid) * 128;
                split32(p[(k + tig)     ^ swa], bh[jj][0], bl[jj][0]);
                split32(p[(k + tig + 4) ^ swa], bh[jj][1], bl[jj][1]);
            }
            #pragma unroll
            for (int i = 0; i < 2; i++)
                #pragma unroll
                for (int jj = 0; jj < 4; jj++) {
                    MMA_TF32(sa[i][jj], ah[i][0], ah[i][1], ah[i][2], ah[i][3],
                             bl[jj][0], bl[jj][1]);
                    MMA_TF32(sa[i][jj], alo[i][0], alo[i][1], alo[i][2], alo[i][3],
                             bh[jj][0], bh[jj][1]);
                    MMA_TF32(sa[i][jj], ah[i][0], ah[i][1], ah[i][2], ah[i][3],
                             bh[jj][0], bh[jj][1]);
                }
        }

        #pragma unroll
        for (int i = 0; i < 2; i++) {
            int m0 = wm * 32 + i * 16 + gid;
            #pragma unroll
            for (int jj = 0; jj < 4; jj++) {
                int c0 = (wn * 32 + jj * 8 + tig * 2) ^ swa;
                *(float2*)&Ps[(size_t)m0 * 64 + c0] =
                    make_float2(sa[i][jj][0], sa[i][jj][1]);
                *(float2*)&Ps[(size_t)(m0 + 8) * 64 + c0] =
                    make_float2(sa[i][jj][2], sa[i][jj][3]);
            }
        }
        __syncthreads();

        {
            const int r  = myr;
            const int sw = (r & 7) << 2;
            float* prow = Ps + (size_t)r * 64;
            const int gq = qi * 128 + r;
            const bool needm = (j >= 2 * qi);
            float4 vv[8];
            float tmax = -1e30f;
            #pragma unroll
            for (int q4 = 0; q4 < 8; q4++) {
                int c = hf * 32 + q4 * 4;
                float4 t = *(float4*)&prow[c ^ sw];
                t.x *= scale; t.y *= scale; t.z *= scale; t.w *= scale;
                if (needm) {
                    int gk = j * 64 + c;
                    if (gk + 0 > gq) t.x = -1e30f;
                    if (gk + 1 > gq) t.y = -1e30f;
                    if (gk + 2 > gq) t.z = -1e30f;
                    if (gk + 3 > gq) t.w = -1e30f;
                }
                vv[q4] = t;
                tmax = fmaxf(tmax, fmaxf(fmaxf(t.x, t.y), fmaxf(t.z, t.w)));
            }
            tmax = fmaxf(tmax, __shfl_xor_sync(0xffffffffu, tmax, 1));
            float mnew  = fmaxf(m_r, tmax);
            float alpha = __expf(m_r - mnew);
            float lsum = 0.0f;
            #pragma unroll
            for (int q4 = 0; q4 < 8; q4++) {
                float4 t = vv[q4];
                t.x = __expf(t.x - mnew); t.y = __expf(t.y - mnew);
                t.z = __expf(t.z - mnew); t.w = __expf(t.w - mnew);
                lsum += t.x + t.y + t.z + t.w;
                int c = hf * 32 + q4 * 4;
                *(float4*)&prow[c ^ sw] = t;
            }
            lsum += __shfl_xor_sync(0xffffffffu, lsum, 1);
            m_r = mnew;
            l_r = l_r * alpha + lsum;
            if (hf == 0) Al[r] = alpha;
        }
        __syncthreads();

        #pragma unroll
        for (int i = 0; i < 2; i++) {
            float a0 = Al[wm * 32 + i * 16 + gid];
            float a1 = Al[wm * 32 + i * 16 + 8 + gid];
            #pragma unroll
            for (int jj = 0; jj < 8; jj++) {
                acc_o[i][jj][0] *= a0; acc_o[i][jj][1] *= a0;
                acc_o[i][jj][2] *= a1; acc_o[i][jj][3] *= a1;
            }
        }

        const float* vb = Vs + buf * 8192;
        #pragma unroll
        for (int ks = 0; ks < 8; ks++) {
            const int k = ks * 8;
            unsigned ah[2][4], alo[2][4];
            #pragma unroll
            for (int i = 0; i < 2; i++) {
                const float* p  = Ps + (size_t)(wm * 32 + i * 16 + gid) * 64;
                const float* p2 = p + 8 * 64;
                split32(p [(k + tig)     ^ swa], ah[i][0], alo[i][0]);
                split32(p2[(k + tig)     ^ swa], ah[i][1], alo[i][1]);
                split32(p [(k + tig + 4) ^ swa], ah[i][2], alo[i][2]);
                split32(p2[(k + tig + 4) ^ swa], ah[i][3], alo[i][3]);
            }
            #pragma unroll
            for (int half = 0; half < 2; half++) {
                unsigned bh[4][2], bl[4][2];
                #pragma unroll
                for (int jj = 0; jj < 4; jj++) {
                    int n = wn * 64 + (half * 4 + jj) * 8 + gid;
                    split32(vb[(size_t)(k + tig)     * 128 + (n ^ swv)],
                            bh[jj][0], bl[jj][0]);
                    split32(vb[(size_t)(k + tig + 4) * 128 + (n ^ swv)],
                            bh[jj][1], bl[jj][1]);
                }
                #pragma unroll
                for (int i = 0; i < 2; i++)
                    #pragma unroll
                    for (int jj = 0; jj < 4; jj++) {
                        float* d = acc_o[i][half * 4 + jj];
                        MMA_TF32(d, ah[i][0], ah[i][1], ah[i][2], ah[i][3],
                                 bl[jj][0], bl[jj][1]);
                        MMA_TF32(d, alo[i][0], alo[i][1], alo[i][2], alo[i][3],
                                 bh[jj][0], bh[jj][1]);
                        MMA_TF32(d, ah[i][0], ah[i][1], ah[i][2], ah[i][3],
                                 bh[jj][0], bh[jj][1]);
                    }
            }
        }
    }

    __syncthreads();
    if (hf == 0) Al[myr] = 1.0f / l_r;
    __syncthreads();

    #pragma unroll
    for (int i = 0; i < 2; i++) {
        int m0 = wm * 32 + i * 16 + gid;
        float li0 = Al[m0], li1 = Al[m0 + 8];
        int gr = qi * 128 + m0;
        float* ob  = O + ((size_t)(b * L_) + gr) * D_ + h * HD_;
        float* ob2 = ob + (size_t)8 * D_;
        #pragma unroll
        for (int jj = 0; jj < 8; jj++) {
            int c = wn * 64 + jj * 8 + tig * 2;
            *(float2*)&ob [c] = make_float2(acc_o[i][jj][0] * li0,
                                            acc_o[i][jj][1] * li0);
            *(float2*)&ob2[c] = make_float2(acc_o[i][jj][2] * li1,
                                            acc_o[i][jj][3] * li1);
        }
    }
}

// ---------------- launch ---------------------------------------------------
extern "C" void kernel_launch(void* const* d_in, const int* in_sizes, int n_in,
                              void* d_out, int out_size)
{
    (void)in_sizes; (void)n_in; (void)out_size;
    const float* x      = (const float*)d_in[0];
    const float* ln1_w  = (const float*)d_in[1];
    const float* q_w    = (const float*)d_in[2];
    const float* q_b    = (const float*)d_in[3];
    const float* k_w    = (const float*)d_in[4];
    const float* k_b    = (const float*)d_in[5];
    const float* v_w    = (const float*)d_in[6];
    const float* v_b    = (const float*)d_in[7];
    const float* o_w    = (const float*)d_in[8];
    const float* ln2_w  = (const float*)d_in[9];
    const float* gate_w = (const float*)d_in[10];
    const float* up_w   = (const float*)d_in[11];
    const float* down_w = (const float*)d_in[12];
    float* out = (float*)d_out;

    float *q, *k, *v, *att, *x1, *gate, *up;
    __nv_bfloat16 *hs, *as_, *h2s, *gs, *qws, *kws, *vws, *ows, *gws, *uws, *dws;
    cudaGetSymbolAddress((void**)&q,    g_q);
    cudaGetSymbolAddress((void**)&k,    g_k);
    cudaGetSymbolAddress((void**)&v,    g_v);
    cudaGetSymbolAddress((void**)&att,  g_att);
    cudaGetSymbolAddress((void**)&x1,   g_x1);
    cudaGetSymbolAddress((void**)&gate, g_gate);
    cudaGetSymbolAddress((void**)&up,   g_up);
    cudaGetSymbolAddress((void**)&hs,   g_hs);
    cudaGetSymbolAddress((void**)&as_,  g_as);
    cudaGetSymbolAddress((void**)&h2s,  g_h2s);
    cudaGetSymbolAddress((void**)&gs,   g_gs);
    cudaGetSymbolAddress((void**)&qws,  g_qws);
    cudaGetSymbolAddress((void**)&kws,  g_kws);
    cudaGetSymbolAddress((void**)&vws,  g_vws);
    cudaGetSymbolAddress((void**)&ows,  g_ows);
    cudaGetSymbolAddress((void**)&gws,  g_gws);
    cudaGetSymbolAddress((void**)&uws,  g_uws);
    cudaGetSymbolAddress((void**)&dws,  g_dws);

    cudaFuncSetAttribute(fattn_kernel, cudaFuncAttributeMaxDynamicSharedMemorySize, ATT2_SMEM);
    cudaFuncSetAttribute(bgemm_kernel<true , false>, cudaFuncAttributeMaxDynamicSharedMemorySize, GEMM_SMEM);
    cudaFuncSetAttribute(bgemm_kernel<false, true >, cudaFuncAttributeMaxDynamicSharedMemorySize, GEMM_SMEM);
    cudaFuncSetAttribute(bgemm_kernel<false, false>, cudaFuncAttributeMaxDynamicSharedMemorySize, GEMM_SMEM);

    // 0. split weights (bf16x2 tiled)
    split_kernel<<<dim3(4, D_ ), 256>>>(q_w,    qws, D_);
    split_kernel<<<dim3(4, KD_), 256>>>(k_w,    kws, D_);
    split_kernel<<<dim3(4, KD_), 256>>>(v_w,    vws, D_);
    split_kernel<<<dim3(4, D_ ), 256>>>(o_w,    ows, D_);
    split_kernel<<<dim3(4, F_ ), 256>>>(gate_w, gws, D_);
    split_kernel<<<dim3(4, F_ ), 256>>>(up_w,   uws, D_);
    split_kernel<<<dim3(11, D_), 256>>>(down_w, dws, F_);

    // 1. RMSNorm 1 -> split h
    rmsnorm_split_kernel<<<M_, 256>>>(x, ln1_w, hs);
    // 2-4. Q, K, V projections (bf16x2 tensor cores)
    bgemm_kernel<true , false><<<dim3(D_  / BN, M_ / BM), 256, GEMM_SMEM>>>(hs, qws, q_b, nullptr, q, M_, D_ , D_);
    bgemm_kernel<true , false><<<dim3(KD_ / BN, M_ / BM), 256, GEMM_SMEM>>>(hs, kws, k_b, nullptr, k, M_, KD_, D_);
    bgemm_kernel<true , false><<<dim3(KD_ / BN, M_ / BM), 256, GEMM_SMEM>>>(hs, vws, v_b, nullptr, v, M_, KD_, D_);
    // 5. causal GQA attention (3xTF32)
    fattn_kernel<<<dim3(L_ / 128, H_, B_), 256, ATT2_SMEM>>>(q, k, v, att);
    // 6. split att, O projection + residual (x)
    split_kernel<<<dim3(4, M_), 256>>>(att, as_, D_);
    bgemm_kernel<false, true ><<<dim3(D_ / BN, M_ / BM), 256, GEMM_SMEM>>>(as_, ows, nullptr, x, x1, M_, D_, D_);
    // 7. RMSNorm 2 -> split h2
    rmsnorm_split_kernel<<<M_, 256>>>(x1, ln2_w, h2s);
    // 8-9. gate / up projections
    bgemm_kernel<false, false><<<dim3(F_ / BN, M_ / BM), 256, GEMM_SMEM>>>(h2s, gws, nullptr, nullptr, gate, M_, F_, D_);
    bgemm_kernel<false, false><<<dim3(F_ / BN, M_ / BM), 256, GEMM_SMEM>>>(h2s, uws, nullptr, nullptr, up  , M_, F_, D_);
    // 10. silu(gate)*up -> split
    silu_mul_split_kernel<<<dim3(F_ / 512, M_), 256>>>(gate, up, gs);
    // 11. down projection + residual (x1) -> output
    bgemm_kernel<false, true ><<<dim3(D_ / BN, M_ / BM), 256, GEMM_SMEM>>>(gs, dws, nullptr, x1, out, M_, D_, F_);
}